// round 1
// baseline (speedup 1.0000x reference)
#include <cuda_runtime.h>
#include <math.h>

#define CB 256
#define CL 256
#define CS 253
#define CD 768
#define CH 128

// ---- scratch (static device globals; no allocation at launch time) ----
__device__ float g_M[CD * CD];                 // s * WQ @ WK^T
__device__ float g_q[(size_t)CB * CL * CD];    // ctx @ M   (201 MB)
__device__ float g_v[CB * 256];                // masked v, padded to 256/batch
__device__ float g_x[CB * CL];                 // attention output vector

__device__ __forceinline__ unsigned f2tf(float f) {
  unsigned r;
  asm("cvt.rna.tf32.f32 %0, %1;" : "=r"(r) : "f"(f));
  return r;
}

__device__ __forceinline__ void mma8(float c[4], const unsigned a[4], const unsigned b[2]) {
  asm volatile(
      "mma.sync.aligned.m16n8k8.row.col.f32.tf32.tf32.f32 "
      "{%0,%1,%2,%3}, {%4,%5,%6,%7}, {%8,%9}, {%0,%1,%2,%3};"
      : "+f"(c[0]), "+f"(c[1]), "+f"(c[2]), "+f"(c[3])
      : "r"(a[0]), "r"(a[1]), "r"(a[2]), "r"(a[3]), "r"(b[0]), "r"(b[1]));
}

// =====================================================================
// Generic 128x128x32 TF32 GEMM. C[M,N] = cscale * A[M,K] @ op(B)
// BT=false: B is [K,N] (NN). BT=true: B is [N,K] (NT). Row-major fp32.
// 256 threads = 8 warps (4x2); warp tile 32x64; double-buffered smem.
// =====================================================================
template <bool BT>
__global__ void __launch_bounds__(256, 1)
gemm_tf32(const float* __restrict__ A, const float* __restrict__ Bm,
          float* __restrict__ C, int M, int N, int K, float cscale) {
  extern __shared__ unsigned smem_u[];
  constexpr int ASTR = 36;   // 32 + 4 pad
  constexpr int BSTR = 132;  // 128 + 4 pad
  unsigned* As = smem_u;                   // [2][128][ASTR]
  unsigned* Bs = smem_u + 2 * 128 * ASTR;  // [2][32][BSTR]

  const int tid = threadIdx.x;
  const int lane = tid & 31, warp = tid >> 5;
  const int wm = warp >> 1, wn = warp & 1;
  const int grp = lane >> 2, qd = lane & 3;
  const int bm = blockIdx.y, bn = blockIdx.x;

  const float* Ag = A + (size_t)bm * 128 * K;

  float acc[2][8][4];
#pragma unroll
  for (int i = 0; i < 2; i++)
#pragma unroll
    for (int j = 0; j < 8; j++)
#pragma unroll
      for (int t = 0; t < 4; t++) acc[i][j][t] = 0.f;

  float4 ra[4], rb[4];

  auto ldA = [&](int kt) {
#pragma unroll
    for (int i = 0; i < 4; i++) {
      int f = tid + i * 256;
      int r = f >> 3, c = f & 7;
      ra[i] = *(reinterpret_cast<const float4*>(Ag + (size_t)r * K + kt * 32) + c);
    }
  };
  auto ldB = [&](int kt) {
#pragma unroll
    for (int i = 0; i < 4; i++) {
      int f = tid + i * 256;
      if (!BT) {
        int r = f >> 5, c = f & 31;
        rb[i] = *(reinterpret_cast<const float4*>(Bm + (size_t)(kt * 32 + r) * N + bn * 128) + c);
      } else {
        int r = f >> 3, c = f & 7;
        rb[i] = *(reinterpret_cast<const float4*>(Bm + (size_t)(bn * 128 + r) * K + kt * 32) + c);
      }
    }
  };
  auto stA = [&](int buf) {
    unsigned* ap = As + buf * 128 * ASTR;
#pragma unroll
    for (int i = 0; i < 4; i++) {
      int f = tid + i * 256;
      int r = f >> 3, c = f & 7;
      unsigned* p = ap + r * ASTR + c * 4;
      p[0] = f2tf(ra[i].x); p[1] = f2tf(ra[i].y); p[2] = f2tf(ra[i].z); p[3] = f2tf(ra[i].w);
    }
  };
  auto stB = [&](int buf) {
    unsigned* bp = Bs + buf * 32 * BSTR;
#pragma unroll
    for (int i = 0; i < 4; i++) {
      int f = tid + i * 256;
      if (!BT) {
        int r = f >> 5, c = f & 31;
        unsigned* p = bp + r * BSTR + c * 4;
        p[0] = f2tf(rb[i].x); p[1] = f2tf(rb[i].y); p[2] = f2tf(rb[i].z); p[3] = f2tf(rb[i].w);
      } else {  // transpose into Bs[k][n]
        int r = f >> 3, c = f & 7;
        bp[(c * 4 + 0) * BSTR + r] = f2tf(rb[i].x);
        bp[(c * 4 + 1) * BSTR + r] = f2tf(rb[i].y);
        bp[(c * 4 + 2) * BSTR + r] = f2tf(rb[i].z);
        bp[(c * 4 + 3) * BSTR + r] = f2tf(rb[i].w);
      }
    }
  };
  auto compute = [&](int buf) {
    const unsigned* ap = As + buf * 128 * ASTR;
    const unsigned* bp = Bs + buf * 32 * BSTR;
#pragma unroll
    for (int ks = 0; ks < 4; ks++) {
      unsigned afr[2][4];
#pragma unroll
      for (int mi = 0; mi < 2; mi++) {
        int row = wm * 32 + mi * 16 + grp;
        afr[mi][0] = ap[row * ASTR + ks * 8 + qd];
        afr[mi][1] = ap[(row + 8) * ASTR + ks * 8 + qd];
        afr[mi][2] = ap[row * ASTR + ks * 8 + qd + 4];
        afr[mi][3] = ap[(row + 8) * ASTR + ks * 8 + qd + 4];
      }
#pragma unroll
      for (int ni = 0; ni < 8; ni++) {
        int col = wn * 64 + ni * 8 + grp;
        unsigned bfr[2];
        bfr[0] = bp[(ks * 8 + qd) * BSTR + col];
        bfr[1] = bp[(ks * 8 + qd + 4) * BSTR + col];
        mma8(acc[0][ni], afr[0], bfr);
        mma8(acc[1][ni], afr[1], bfr);
      }
    }
  };

  const int KT = K / 32;
  ldA(0); ldB(0); stA(0); stB(0);
  __syncthreads();
  for (int kt = 0; kt < KT; ++kt) {
    if (kt + 1 < KT) { ldA(kt + 1); ldB(kt + 1); }
    compute(kt & 1);
    if (kt + 1 < KT) { stA((kt + 1) & 1); stB((kt + 1) & 1); }
    __syncthreads();
  }

#pragma unroll
  for (int mi = 0; mi < 2; mi++)
#pragma unroll
    for (int ni = 0; ni < 8; ni++) {
      int r0 = bm * 128 + wm * 32 + mi * 16 + grp;
      int c0 = bn * 128 + wn * 64 + ni * 8 + qd * 2;
      float* cp = C + (size_t)r0 * N + c0;
      cp[0] = acc[mi][ni][0] * cscale;
      cp[1] = acc[mi][ni][1] * cscale;
      cp += (size_t)8 * N;
      cp[0] = acc[mi][ni][2] * cscale;
      cp[1] = acc[mi][ni][3] * cscale;
    }
}

// =====================================================================
// v' kernel: v'[b,s] = cand_mask[b,s] ? dot(cand[b,s,:], WV) : 0
// padded to 256 slots per batch (slots 253..255 = 0). One warp per row;
// masked rows skip the 3KB read entirely (~halves this pass's BW).
// =====================================================================
__global__ void v_kernel(const float* __restrict__ cand,
                         const int* __restrict__ cand_mask,
                         const float* __restrict__ WV) {
  int gw = (blockIdx.x * blockDim.x + threadIdx.x) >> 5;
  int lane = threadIdx.x & 31;
  if (gw >= CB * 256) return;
  int b = gw >> 8, s = gw & 255;
  float out = 0.f;
  if (s < CS && cand_mask[b * CS + s]) {
    const float* row = cand + ((size_t)b * CS + s) * CD;
    float a = 0.f;
    for (int d = lane; d < CD; d += 32) a += row[d] * WV[d];
#pragma unroll
    for (int o = 16; o > 0; o >>= 1) a += __shfl_xor_sync(0xffffffffu, a, o);
    out = a;
  }
  if (lane == 0) g_v[b * 256 + s] = out;
}

// =====================================================================
// Fused attention: per CTA (b, 128-row L-tile):
//   P[128,256] = q''_tile @ cand_b^T  (tf32 mma, K=768)
//   x[l] = ctx_mask[l] * sum_s sigmoid(P[l,s]) * v'[s]
// Logits never touch memory; accumulators live in mma register fragments.
// =====================================================================
__global__ void __launch_bounds__(256, 1)
attn_fused(const float* __restrict__ cand, const int* __restrict__ ctx_mask) {
  extern __shared__ unsigned smem_u[];
  constexpr int ASTR = 36;
  constexpr int BSTR = 260;  // 256 + 4 pad
  unsigned* As = smem_u;               // [128][ASTR]
  unsigned* Bs = smem_u + 128 * ASTR;  // [32][BSTR]
  float* v_s = reinterpret_cast<float*>(smem_u + 128 * ASTR + 32 * BSTR);  // [256]
  float* x_s = v_s + 256;                                                  // [128]

  const int b = blockIdx.y;
  const int l0 = blockIdx.x * 128;
  const int tid = threadIdx.x;
  const int lane = tid & 31, warp = tid >> 5;
  const int wm = warp >> 1, wn = warp & 1;
  const int grp = lane >> 2, qd = lane & 3;

  const float* Ag = g_q + ((size_t)b * CL + l0) * CD;
  const float* Bg = cand + (size_t)b * CS * CD;

  v_s[tid] = g_v[b * 256 + tid];
  if (tid < 128) x_s[tid] = 0.f;

  float acc[2][16][4];
#pragma unroll
  for (int i = 0; i < 2; i++)
#pragma unroll
    for (int j = 0; j < 16; j++)
#pragma unroll
      for (int t = 0; t < 4; t++) acc[i][j][t] = 0.f;

  for (int kt = 0; kt < CD / 32; ++kt) {
    __syncthreads();  // prev compute done (and covers v_s/x_s init at kt=0)
#pragma unroll
    for (int i = 0; i < 4; i++) {
      int f = tid + i * 256;
      int r = f >> 3, c = f & 7;
      float4 v4 = *(reinterpret_cast<const float4*>(Ag + (size_t)r * CD + kt * 32) + c);
      unsigned* p = As + r * ASTR + c * 4;
      p[0] = f2tf(v4.x); p[1] = f2tf(v4.y); p[2] = f2tf(v4.z); p[3] = f2tf(v4.w);
    }
#pragma unroll
    for (int i = 0; i < 8; i++) {
      int f = tid + i * 256;
      int r = f >> 3, c = f & 7;  // r = s index 0..255
      float4 v4 = make_float4(0.f, 0.f, 0.f, 0.f);
      if (r < CS)
        v4 = *(reinterpret_cast<const float4*>(Bg + (size_t)r * CD + kt * 32) + c);
      Bs[(c * 4 + 0) * BSTR + r] = f2tf(v4.x);
      Bs[(c * 4 + 1) * BSTR + r] = f2tf(v4.y);
      Bs[(c * 4 + 2) * BSTR + r] = f2tf(v4.z);
      Bs[(c * 4 + 3) * BSTR + r] = f2tf(v4.w);
    }
    __syncthreads();
#pragma unroll
    for (int ks = 0; ks < 4; ks++) {
      unsigned afr[2][4];
#pragma unroll
      for (int mi = 0; mi < 2; mi++) {
        int row = wm * 32 + mi * 16 + grp;
        afr[mi][0] = As[row * ASTR + ks * 8 + qd];
        afr[mi][1] = As[(row + 8) * ASTR + ks * 8 + qd];
        afr[mi][2] = As[row * ASTR + ks * 8 + qd + 4];
        afr[mi][3] = As[(row + 8) * ASTR + ks * 8 + qd + 4];
      }
#pragma unroll
      for (int ni = 0; ni < 16; ni++) {
        int col = wn * 128 + ni * 8 + grp;
        unsigned bfr[2];
        bfr[0] = Bs[(ks * 8 + qd) * BSTR + col];
        bfr[1] = Bs[(ks * 8 + qd + 4) * BSTR + col];
        mma8(acc[0][ni], afr[0], bfr);
        mma8(acc[1][ni], afr[1], bfr);
      }
    }
  }

  // epilogue: x += sigmoid(P) * v'  (padded cols have v'=0 -> no effect)
  float xp[2][2] = {{0.f, 0.f}, {0.f, 0.f}};
#pragma unroll
  for (int mi = 0; mi < 2; mi++)
#pragma unroll
    for (int ni = 0; ni < 16; ni++) {
      int c0 = wn * 128 + ni * 8 + qd * 2;
      float va = v_s[c0], vb = v_s[c0 + 1];
      float s0 = 1.f / (1.f + __expf(-acc[mi][ni][0]));
      float s1 = 1.f / (1.f + __expf(-acc[mi][ni][1]));
      float s2 = 1.f / (1.f + __expf(-acc[mi][ni][2]));
      float s3 = 1.f / (1.f + __expf(-acc[mi][ni][3]));
      xp[mi][0] += s0 * va + s1 * vb;
      xp[mi][1] += s2 * va + s3 * vb;
    }
#pragma unroll
  for (int mi = 0; mi < 2; mi++)
#pragma unroll
    for (int rs = 0; rs < 2; rs++) {
      float v = xp[mi][rs];
      v += __shfl_xor_sync(0xffffffffu, v, 1);
      v += __shfl_xor_sync(0xffffffffu, v, 2);
      if (qd == 0) atomicAdd(&x_s[wm * 32 + mi * 16 + rs * 8 + grp], v);
    }
  __syncthreads();
  if (tid < 128) {
    int l = l0 + tid;
    g_x[b * CL + l] = ctx_mask[b * CL + l] ? x_s[tid] : 0.f;
  }
}

// =====================================================================
// Head: y[b,:] = (x_b @ W1 + b1) @ W2 + b2.  One CTA per batch.
// =====================================================================
__global__ void head_kernel(const float* __restrict__ W1, const float* __restrict__ b1,
                            const float* __restrict__ W2, const float* __restrict__ b2,
                            float* __restrict__ out) {
  __shared__ float xs[CL];
  __shared__ float hs[CH];
  int b = blockIdx.x, tid = threadIdx.x;  // 128 threads
  xs[tid] = g_x[b * CL + tid];
  xs[tid + 128] = g_x[b * CL + tid + 128];
  __syncthreads();
  float h = b1[tid];
  for (int l = 0; l < CL; l++) h += xs[l] * W1[l * CH + tid];
  hs[tid] = h;
  __syncthreads();
  if (tid < 5) {
    float y = b2[tid];
    for (int k = 0; k < CH; k++) y += hs[k] * W2[k * 5 + tid];
    out[b * 5 + tid] = y;
  }
}

extern "C" void kernel_launch(void* const* d_in, const int* in_sizes, int n_in,
                              void* d_out, int out_size) {
  const float* ctx = (const float*)d_in[0];
  const float* cand = (const float*)d_in[1];
  const int* ctx_mask = (const int*)d_in[2];
  const int* cand_mask = (const int*)d_in[3];
  const float* WK = (const float*)d_in[4];
  const float* WQ = (const float*)d_in[5];
  const float* WV = (const float*)d_in[6];
  const float* W1 = (const float*)d_in[7];
  const float* b1 = (const float*)d_in[8];
  const float* W2 = (const float*)d_in[9];
  const float* b2 = (const float*)d_in[10];
  float* out = (float*)d_out;
  (void)in_sizes; (void)n_in; (void)out_size;

  constexpr int GEMM_SMEM = (2 * 128 * 36 + 2 * 32 * 132) * 4;           // 70656 B
  constexpr int ATTN_SMEM = (128 * 36 + 32 * 260) * 4 + 384 * 4;          // 53248 B

  cudaFuncSetAttribute(gemm_tf32<true>, cudaFuncAttributeMaxDynamicSharedMemorySize, GEMM_SMEM);
  cudaFuncSetAttribute(gemm_tf32<false>, cudaFuncAttributeMaxDynamicSharedMemorySize, GEMM_SMEM);
  cudaFuncSetAttribute(attn_fused, cudaFuncAttributeMaxDynamicSharedMemorySize, ATTN_SMEM);

  void* pM = nullptr;
  void* pQ = nullptr;
  cudaGetSymbolAddress(&pM, g_M);
  cudaGetSymbolAddress(&pQ, g_q);

  float scale = 1.0f / sqrtf((float)CD);

  // K0: M = scale * WQ @ WK^T   (NT)
  gemm_tf32<true><<<dim3(CD / 128, CD / 128), 256, GEMM_SMEM>>>(
      WQ, WK, (float*)pM, CD, CD, CD, scale);

  // K1b: masked v, padded per batch
  v_kernel<<<(CB * 256) / 8, 256>>>(cand, cand_mask, WV);

  // K1: q'' = ctx @ M   (NN) -- the dominant GEMM
  gemm_tf32<false><<<dim3(CD / 128, (CB * CL) / 128), 256, GEMM_SMEM>>>(
      ctx, (const float*)pM, (float*)pQ, CB * CL, CD, CD, 1.0f);

  // K2: fused logits -> sigmoid -> x
  attn_fused<<<dim3(2, CB), 256, ATTN_SMEM>>>(cand, ctx_mask);

  // K3: head MLP -> y
  head_kernel<<<CB, CH>>>(W1, b1, W2, b2, out);
}

// round 3
// speedup vs baseline: 1.7848x; 1.7848x over previous
#include <cuda_runtime.h>
#include <math.h>
#include <stdint.h>

#define CB 256
#define CL 256
#define CS 253
#define CD 768
#define CH 128
#define ROWCAP (CB * CL + 128)  // 65664 compacted-row capacity (incl. pad)

// ---- scratch (static device globals; no allocation at launch time) ----
__device__ __align__(256) float g_M[CD * CD];                       // s*WQ@WK^T, tf32-rounded
__device__ __align__(256) float g_ctx_c[(size_t)ROWCAP * CD];       // compacted ctx rows, rounded
__device__ __align__(256) float g_qc[(size_t)ROWCAP * CD];          // compacted q'' rows, rounded
__device__ __align__(256) float g_cand_c[(size_t)CB * 256 * CD];    // per-batch compacted cand, rounded
__device__ float g_v[CB * 256];
__device__ float g_x[CB * CL];
__device__ int g_rowmap[ROWCAP];   // compact row -> b*256+l  (-1 sentinel)
__device__ int g_colmap[CB * 256]; // per-batch compact col -> s (-1 sentinel)
__device__ int g_start[CB];
__device__ int g_cnt[CB];
__device__ int g_cnt_s[CB];
__device__ int g_total;

// =====================================================================
// helpers
// =====================================================================
__device__ __forceinline__ unsigned f2tf(float f) {
  unsigned r;
  asm("cvt.rna.tf32.f32 %0, %1;" : "=r"(r) : "f"(f));
  return r;
}
__device__ __forceinline__ float frnd(float f) { return __uint_as_float(f2tf(f)); }

__device__ __forceinline__ uint32_t smem_u32(const void* p) {
  uint32_t a;
  asm("{ .reg .u64 t; cvta.to.shared.u64 t, %1; cvt.u32.u64 %0, t; }" : "=r"(a) : "l"(p));
  return a;
}

__device__ __forceinline__ void cp16(uint32_t dst, const void* src) {
  asm volatile("cp.async.cg.shared.global [%0], [%1], 16;" ::"r"(dst), "l"(src) : "memory");
}
#define CP_COMMIT() asm volatile("cp.async.commit_group;" ::: "memory")
#define CP_WAIT1() asm volatile("cp.async.wait_group 1;" ::: "memory")

__device__ __forceinline__ void mma8(float c[4], const unsigned a[4], const unsigned b[2]) {
  asm volatile(
      "mma.sync.aligned.m16n8k8.row.col.f32.tf32.tf32.f32 "
      "{%0,%1,%2,%3}, {%4,%5,%6,%7}, {%8,%9}, {%0,%1,%2,%3};"
      : "+f"(c[0]), "+f"(c[1]), "+f"(c[2]), "+f"(c[3])
      : "r"(a[0]), "r"(a[1]), "r"(a[2]), "r"(a[3]), "r"(b[0]), "r"(b[1]));
}

// =====================================================================
// scan1: per-batch mask counts + global prefix over ctx counts. 1 block.
// =====================================================================
__global__ void scan1(const int* __restrict__ ctx_mask, const int* __restrict__ cand_mask) {
  __shared__ int sc[CB];
  int b = threadIdx.x;
  int c = 0;
  for (int l = 0; l < CL; l++) c += ctx_mask[b * CL + l];
  int cs = 0;
  for (int s = 0; s < CS; s++) cs += cand_mask[b * CS + s];
  g_cnt[b] = c;
  g_cnt_s[b] = cs;
  sc[b] = c;
  __syncthreads();
  for (int off = 1; off < CB; off <<= 1) {
    int v = (b >= off) ? sc[b - off] : 0;
    __syncthreads();
    sc[b] += v;
    __syncthreads();
  }
  g_start[b] = sc[b] - c;
  if (b == CB - 1) g_total = sc[b];
}

// =====================================================================
// scan2: build rowmap/colmap via intra-block ranks; zero g_x; sentinels.
// grid = 256 (one block per batch), 256 threads.
// =====================================================================
__global__ void scan2(const int* __restrict__ ctx_mask, const int* __restrict__ cand_mask) {
  __shared__ int wsum[8], wsum2[8];
  int b = blockIdx.x, t = threadIdx.x, lane = t & 31, w = t >> 5;
  g_x[b * CL + t] = 0.f;
  g_colmap[b * 256 + t] = -1;
  int m = ctx_mask[b * CL + t];
  unsigned bal = __ballot_sync(~0u, m != 0);
  int wr = __popc(bal & ((1u << lane) - 1));
  int m2 = (t < CS) ? cand_mask[b * CS + t] : 0;
  unsigned bal2 = __ballot_sync(~0u, m2 != 0);
  int wr2 = __popc(bal2 & ((1u << lane) - 1));
  if (lane == 0) {
    wsum[w] = __popc(bal);
    wsum2[w] = __popc(bal2);
  }
  __syncthreads();
  int off = 0, off2 = 0;
  for (int i = 0; i < w; i++) {
    off += wsum[i];
    off2 += wsum2[i];
  }
  if (m) g_rowmap[g_start[b] + off + wr] = b * CL + t;
  if (m2) g_colmap[b * 256 + off2 + wr2] = t;
  if (b == 0 && t < 128) g_rowmap[g_total + t] = -1;  // pad region
}

// =====================================================================
// compact_ctx: g_ctx_c[i] = rnd(ctx[rowmap[i]]) (zeros for sentinel).
// grid = ROWCAP blocks of 192 threads (768 floats = 192 float4).
// =====================================================================
__global__ void compact_ctx(const float* __restrict__ ctx) {
  int i = blockIdx.x;
  int ptot = (g_total + 127) & ~127;
  if (i >= ptot) return;
  int src = g_rowmap[i];
  int t = threadIdx.x;
  float4 v = make_float4(0.f, 0.f, 0.f, 0.f);
  if (src >= 0) v = ((const float4*)(ctx + (size_t)src * CD))[t];
  v.x = frnd(v.x); v.y = frnd(v.y); v.z = frnd(v.z); v.w = frnd(v.w);
  ((float4*)(g_ctx_c + (size_t)i * CD))[t] = v;
}

// =====================================================================
// compact_cand: g_cand_c[b,j] = rnd(cand[b, colmap[b,j]]) or zeros.
// grid = (256 j-slots, 256 batches), 192 threads. Skips unused tiles.
// =====================================================================
__global__ void compact_cand(const float* __restrict__ cand) {
  int b = blockIdx.y, j = blockIdx.x;
  int lim = (g_cnt_s[b] > 128) ? 256 : 128;
  if (j >= lim) return;
  int s = g_colmap[b * 256 + j];
  int t = threadIdx.x;
  float4 v = make_float4(0.f, 0.f, 0.f, 0.f);
  if (s >= 0) v = ((const float4*)(cand + ((size_t)b * CS + s) * CD))[t];
  v.x = frnd(v.x); v.y = frnd(v.y); v.z = frnd(v.z); v.w = frnd(v.w);
  ((float4*)(g_cand_c + ((size_t)b * 256 + j) * CD))[t] = v;
}

// =====================================================================
// v'[b,s] = cand_mask[b,s] ? dot(cand[b,s,:], WV) : 0   (padded to 256)
// =====================================================================
__global__ void v_kernel(const float* __restrict__ cand,
                         const int* __restrict__ cand_mask,
                         const float* __restrict__ WV) {
  int gw = (blockIdx.x * blockDim.x + threadIdx.x) >> 5;
  int lane = threadIdx.x & 31;
  if (gw >= CB * 256) return;
  int b = gw >> 8, s = gw & 255;
  float out = 0.f;
  if (s < CS && cand_mask[b * CS + s]) {
    const float* row = cand + ((size_t)b * CS + s) * CD;
    float a = 0.f;
    for (int d = lane; d < CD; d += 32) a += row[d] * WV[d];
#pragma unroll
    for (int o = 16; o > 0; o >>= 1) a += __shfl_xor_sync(0xffffffffu, a, o);
    out = a;
  }
  if (lane == 0) g_v[b * 256 + s] = out;
}

// =====================================================================
// K0: M = scale * WQ @ WK^T (NT, tf32 mma.sync), tf32-rounded store.
// =====================================================================
__global__ void __launch_bounds__(256, 1)
gemm_nt(const float* __restrict__ A, const float* __restrict__ Bm,
        float* __restrict__ C, int M, int N, int K, float cscale) {
  extern __shared__ unsigned smem_u[];
  constexpr int ASTR = 36;
  constexpr int BSTR = 132;
  unsigned* As = smem_u;
  unsigned* Bs = smem_u + 2 * 128 * ASTR;

  const int tid = threadIdx.x;
  const int lane = tid & 31, warp = tid >> 5;
  const int wm = warp >> 1, wn = warp & 1;
  const int grp = lane >> 2, qd = lane & 3;
  const int bm = blockIdx.y, bn = blockIdx.x;

  const float* Agp = A + (size_t)bm * 128 * K;

  float acc[2][8][4];
#pragma unroll
  for (int i = 0; i < 2; i++)
#pragma unroll
    for (int j = 0; j < 8; j++)
#pragma unroll
      for (int t = 0; t < 4; t++) acc[i][j][t] = 0.f;

  float4 ra[4], rb[4];
  auto ldA = [&](int kt) {
#pragma unroll
    for (int i = 0; i < 4; i++) {
      int f = tid + i * 256, r = f >> 3, c = f & 7;
      ra[i] = *(reinterpret_cast<const float4*>(Agp + (size_t)r * K + kt * 32) + c);
    }
  };
  auto ldB = [&](int kt) {
#pragma unroll
    for (int i = 0; i < 4; i++) {
      int f = tid + i * 256, r = f >> 3, c = f & 7;
      rb[i] = *(reinterpret_cast<const float4*>(Bm + (size_t)(bn * 128 + r) * K + kt * 32) + c);
    }
  };
  auto stA = [&](int buf) {
    unsigned* ap = As + buf * 128 * ASTR;
#pragma unroll
    for (int i = 0; i < 4; i++) {
      int f = tid + i * 256, r = f >> 3, c = f & 7;
      unsigned* p = ap + r * ASTR + c * 4;
      p[0] = f2tf(ra[i].x); p[1] = f2tf(ra[i].y); p[2] = f2tf(ra[i].z); p[3] = f2tf(ra[i].w);
    }
  };
  auto stB = [&](int buf) {
    unsigned* bp = Bs + buf * 32 * BSTR;
#pragma unroll
    for (int i = 0; i < 4; i++) {
      int f = tid + i * 256, r = f >> 3, c = f & 7;
      bp[(c * 4 + 0) * BSTR + r] = f2tf(rb[i].x);
      bp[(c * 4 + 1) * BSTR + r] = f2tf(rb[i].y);
      bp[(c * 4 + 2) * BSTR + r] = f2tf(rb[i].z);
      bp[(c * 4 + 3) * BSTR + r] = f2tf(rb[i].w);
    }
  };
  auto compute = [&](int buf) {
    const unsigned* ap = As + buf * 128 * ASTR;
    const unsigned* bp = Bs + buf * 32 * BSTR;
#pragma unroll
    for (int ks = 0; ks < 4; ks++) {
      unsigned afr[2][4];
#pragma unroll
      for (int mi = 0; mi < 2; mi++) {
        int row = wm * 32 + mi * 16 + grp;
        afr[mi][0] = ap[row * ASTR + ks * 8 + qd];
        afr[mi][1] = ap[(row + 8) * ASTR + ks * 8 + qd];
        afr[mi][2] = ap[row * ASTR + ks * 8 + qd + 4];
        afr[mi][3] = ap[(row + 8) * ASTR + ks * 8 + qd + 4];
      }
#pragma unroll
      for (int ni = 0; ni < 8; ni++) {
        int col = wn * 64 + ni * 8 + grp;
        unsigned bfr[2];
        bfr[0] = bp[(ks * 8 + qd) * BSTR + col];
        bfr[1] = bp[(ks * 8 + qd + 4) * BSTR + col];
        mma8(acc[0][ni], afr[0], bfr);
        mma8(acc[1][ni], afr[1], bfr);
      }
    }
  };

  const int KT = K / 32;
  ldA(0); ldB(0); stA(0); stB(0);
  __syncthreads();
  for (int kt = 0; kt < KT; ++kt) {
    if (kt + 1 < KT) { ldA(kt + 1); ldB(kt + 1); }
    compute(kt & 1);
    if (kt + 1 < KT) { stA((kt + 1) & 1); stB((kt + 1) & 1); }
    __syncthreads();
  }

#pragma unroll
  for (int mi = 0; mi < 2; mi++)
#pragma unroll
    for (int ni = 0; ni < 8; ni++) {
      int r0 = bm * 128 + wm * 32 + mi * 16 + grp;
      int c0 = bn * 128 + wn * 64 + ni * 8 + qd * 2;
      float* cp = C + (size_t)r0 * N + c0;
      cp[0] = frnd(acc[mi][ni][0] * cscale);
      cp[1] = frnd(acc[mi][ni][1] * cscale);
      cp += (size_t)8 * N;
      cp[0] = frnd(acc[mi][ni][2] * cscale);
      cp[1] = frnd(acc[mi][ni][3] * cscale);
    }
}

// =====================================================================
// K1 qgemm: q_c[i,:] = ctx_c[i,:] @ M  over compacted rows.
// 128x128 tile, 3-stage cp.async pipeline, 2 CTAs/SM.
// A smem: [128 rows][36 pad], B smem: [32 k][132 pad] (both conflict-free).
// =====================================================================
__global__ void __launch_bounds__(256, 2) qgemm() {
  extern __shared__ char sm[];
  const int tid = threadIdx.x, lane = tid & 31, warp = tid >> 5;
  const int wm = warp >> 1, wn = warp & 1;
  const int grp = lane >> 2, qd = lane & 3;
  const int ptot = (g_total + 127) & ~127;
  const int i0 = blockIdx.y * 128;
  if (i0 >= ptot) return;
  const int bn = blockIdx.x;
  const char* Abase = (const char*)(g_ctx_c + (size_t)i0 * CD);
  const char* Bbase = (const char*)g_M + bn * 512;
  const uint32_t sb = smem_u32(sm);
  constexpr int ASZ = 128 * 144;  // 18432
  constexpr int BSZ = 32 * 528;   // 16896
  constexpr int STG = ASZ + BSZ;  // 35328

  float acc[2][8][4];
#pragma unroll
  for (int i = 0; i < 2; i++)
#pragma unroll
    for (int j = 0; j < 8; j++)
#pragma unroll
      for (int t = 0; t < 4; t++) acc[i][j][t] = 0.f;

  auto issue = [&](int kt) {
    if (kt < 24) {
      int s = kt - (kt / 3) * 3;
      uint32_t ab = sb + s * STG, bb = ab + ASZ;
#pragma unroll
      for (int i = 0; i < 4; i++) {
        int f = tid + i * 256, r = f >> 3, c = f & 7;
        cp16(ab + r * 144 + c * 16, Abase + (size_t)r * 3072 + kt * 128 + c * 16);
      }
#pragma unroll
      for (int i = 0; i < 4; i++) {
        int f = tid + i * 256, k = f >> 5, c = f & 31;
        cp16(bb + k * 528 + c * 16, Bbase + (size_t)(kt * 32 + k) * 3072 + c * 16);
      }
    }
    CP_COMMIT();
  };

  issue(0);
  issue(1);
  for (int kt = 0; kt < 24; ++kt) {
    CP_WAIT1();
    __syncthreads();
    issue(kt + 2);
    const int s = kt - (kt / 3) * 3;
    const unsigned* ap = (const unsigned*)(sm + s * STG);
    const unsigned* bp = (const unsigned*)(sm + s * STG + ASZ);
#pragma unroll
    for (int ks = 0; ks < 4; ks++) {
      unsigned afr[2][4];
#pragma unroll
      for (int mi = 0; mi < 2; mi++) {
        int row = wm * 32 + mi * 16 + grp;
        afr[mi][0] = ap[row * 36 + ks * 8 + qd];
        afr[mi][1] = ap[(row + 8) * 36 + ks * 8 + qd];
        afr[mi][2] = ap[row * 36 + ks * 8 + qd + 4];
        afr[mi][3] = ap[(row + 8) * 36 + ks * 8 + qd + 4];
      }
#pragma unroll
      for (int ni = 0; ni < 8; ni++) {
        int col = wn * 64 + ni * 8 + grp;
        unsigned bfr[2];
        bfr[0] = bp[(ks * 8 + qd) * 132 + col];
        bfr[1] = bp[(ks * 8 + qd + 4) * 132 + col];
        mma8(acc[0][ni], afr[0], bfr);
        mma8(acc[1][ni], afr[1], bfr);
      }
    }
  }

#pragma unroll
  for (int mi = 0; mi < 2; mi++)
#pragma unroll
    for (int ni = 0; ni < 8; ni++) {
      int r = wm * 32 + mi * 16 + grp;
      int c = bn * 128 + wn * 64 + ni * 8 + qd * 2;
      size_t o = (size_t)(i0 + r) * CD + c;
      g_qc[o] = frnd(acc[mi][ni][0]);
      g_qc[o + 1] = frnd(acc[mi][ni][1]);
      o += (size_t)8 * CD;
      g_qc[o] = frnd(acc[mi][ni][2]);
      g_qc[o + 1] = frnd(acc[mi][ni][3]);
    }
}

// =====================================================================
// attn agemm: per (b, mt, nt): logits 128x128 = q_c tile @ cand_c tile^T,
// x[row] += sum_col sigmoid(logit)*v'. 3-stage cp.async, 2 CTAs/SM.
// Both A and B smem: [128 rows][36 pad].
// =====================================================================
__global__ void __launch_bounds__(256, 2) agemm() {
  extern __shared__ char sm[];
  const int b = blockIdx.y;
  const int mt = blockIdx.x >> 1, nt = blockIdx.x & 1;
  const int cnt = g_cnt[b], cs = g_cnt_s[b];
  if (mt * 128 >= cnt || nt * 128 >= cs) return;
  const int start = g_start[b];
  const int tid = threadIdx.x, lane = tid & 31, warp = tid >> 5;
  const int wm = warp >> 1, wn = warp & 1;
  const int grp = lane >> 2, qd = lane & 3;

  float* v_s = (float*)sm;            // [128]
  float* x_s = (float*)(sm + 512);    // [128]
  char* stg = sm + 1024;
  const uint32_t sb = smem_u32(stg);
  constexpr int ASZ = 128 * 144;
  constexpr int STG = 2 * ASZ;  // 36864

  const char* Abase = (const char*)(g_qc + (size_t)(start + mt * 128) * CD);
  const char* Bbase = (const char*)(g_cand_c + ((size_t)b * 256 + nt * 128) * CD);

  if (tid < 128) {
    x_s[tid] = 0.f;
    int cm = g_colmap[b * 256 + nt * 128 + tid];
    v_s[tid] = (cm >= 0) ? g_v[b * 256 + cm] : 0.f;
  }

  float acc[2][8][4];
#pragma unroll
  for (int i = 0; i < 2; i++)
#pragma unroll
    for (int j = 0; j < 8; j++)
#pragma unroll
      for (int t = 0; t < 4; t++) acc[i][j][t] = 0.f;

  auto issue = [&](int kt) {
    if (kt < 24) {
      int s = kt - (kt / 3) * 3;
      uint32_t ab = sb + s * STG, bb = ab + ASZ;
#pragma unroll
      for (int i = 0; i < 4; i++) {
        int f = tid + i * 256, r = f >> 3, c = f & 7;
        cp16(ab + r * 144 + c * 16, Abase + (size_t)r * 3072 + kt * 128 + c * 16);
      }
#pragma unroll
      for (int i = 0; i < 4; i++) {
        int f = tid + i * 256, r = f >> 3, c = f & 7;
        cp16(bb + r * 144 + c * 16, Bbase + (size_t)r * 3072 + kt * 128 + c * 16);
      }
    }
    CP_COMMIT();
  };

  issue(0);
  issue(1);
  for (int kt = 0; kt < 24; ++kt) {
    CP_WAIT1();
    __syncthreads();
    issue(kt + 2);
    const int s = kt - (kt / 3) * 3;
    const unsigned* ap = (const unsigned*)(stg + s * STG);
    const unsigned* bp = (const unsigned*)(stg + s * STG + ASZ);
#pragma unroll
    for (int ks = 0; ks < 4; ks++) {
      unsigned afr[2][4];
#pragma unroll
      for (int mi = 0; mi < 2; mi++) {
        int row = wm * 32 + mi * 16 + grp;
        afr[mi][0] = ap[row * 36 + ks * 8 + qd];
        afr[mi][1] = ap[(row + 8) * 36 + ks * 8 + qd];
        afr[mi][2] = ap[row * 36 + ks * 8 + qd + 4];
        afr[mi][3] = ap[(row + 8) * 36 + ks * 8 + qd + 4];
      }
#pragma unroll
      for (int ni = 0; ni < 8; ni++) {
        int col = wn * 64 + ni * 8 + grp;
        unsigned bfr[2];
        bfr[0] = bp[col * 36 + ks * 8 + qd];
        bfr[1] = bp[col * 36 + ks * 8 + qd + 4];
        mma8(acc[0][ni], afr[0], bfr);
        mma8(acc[1][ni], afr[1], bfr);
      }
    }
  }

  // epilogue: x += sigmoid(logits) * v'
  float xp[2][2] = {{0.f, 0.f}, {0.f, 0.f}};
#pragma unroll
  for (int mi = 0; mi < 2; mi++)
#pragma unroll
    for (int ni = 0; ni < 8; ni++) {
      int c0 = wn * 64 + ni * 8 + qd * 2;
      float va = v_s[c0], vb = v_s[c0 + 1];
      xp[mi][0] += va / (1.f + __expf(-acc[mi][ni][0])) + vb / (1.f + __expf(-acc[mi][ni][1]));
      xp[mi][1] += va / (1.f + __expf(-acc[mi][ni][2])) + vb / (1.f + __expf(-acc[mi][ni][3]));
    }
#pragma unroll
  for (int mi = 0; mi < 2; mi++)
#pragma unroll
    for (int rs = 0; rs < 2; rs++) {
      float v = xp[mi][rs];
      v += __shfl_xor_sync(0xffffffffu, v, 1);
      v += __shfl_xor_sync(0xffffffffu, v, 2);
      if (qd == 0) atomicAdd(&x_s[wm * 32 + mi * 16 + rs * 8 + grp], v);
    }
  __syncthreads();
  if (tid < 128 && mt * 128 + tid < cnt) {
    atomicAdd(&g_x[g_rowmap[start + mt * 128 + tid]], x_s[tid]);
  }
}

// =====================================================================
// Head: y[b,:] = (x_b @ W1 + b1) @ W2 + b2.  One CTA per batch.
// =====================================================================
__global__ void head_kernel(const float* __restrict__ W1, const float* __restrict__ b1,
                            const float* __restrict__ W2, const float* __restrict__ b2,
                            float* __restrict__ out) {
  __shared__ float xs[CL];
  __shared__ float hs[CH];
  int b = blockIdx.x, tid = threadIdx.x;  // 128 threads
  xs[tid] = g_x[b * CL + tid];
  xs[tid + 128] = g_x[b * CL + tid + 128];
  __syncthreads();
  float h = b1[tid];
  for (int l = 0; l < CL; l++) h += xs[l] * W1[l * CH + tid];
  hs[tid] = h;
  __syncthreads();
  if (tid < 5) {
    float y = b2[tid];
    for (int k = 0; k < CH; k++) y += hs[k] * W2[k * 5 + tid];
    out[b * 5 + tid] = y;
  }
}

extern "C" void kernel_launch(void* const* d_in, const int* in_sizes, int n_in,
                              void* d_out, int out_size) {
  const float* ctx = (const float*)d_in[0];
  const float* cand = (const float*)d_in[1];
  const int* ctx_mask = (const int*)d_in[2];
  const int* cand_mask = (const int*)d_in[3];
  const float* WK = (const float*)d_in[4];
  const float* WQ = (const float*)d_in[5];
  const float* WV = (const float*)d_in[6];
  const float* W1 = (const float*)d_in[7];
  const float* b1 = (const float*)d_in[8];
  const float* W2 = (const float*)d_in[9];
  const float* b2 = (const float*)d_in[10];
  float* out = (float*)d_out;
  (void)in_sizes; (void)n_in; (void)out_size;

  constexpr int GEMM_SMEM = (2 * 128 * 36 + 2 * 32 * 132) * 4;  // 70656
  constexpr int QSMEM = 3 * (128 * 144 + 32 * 528);             // 105984
  constexpr int ASMEM = 1024 + 3 * (2 * 128 * 144);             // 111616

  cudaFuncSetAttribute(gemm_nt, cudaFuncAttributeMaxDynamicSharedMemorySize, GEMM_SMEM);
  cudaFuncSetAttribute(qgemm, cudaFuncAttributeMaxDynamicSharedMemorySize, QSMEM);
  cudaFuncSetAttribute(agemm, cudaFuncAttributeMaxDynamicSharedMemorySize, ASMEM);

  void* pM = nullptr;
  cudaGetSymbolAddress(&pM, g_M);

  float scale = 1.0f / sqrtf((float)CD);

  // mask scans + compaction maps
  scan1<<<1, 256>>>(ctx_mask, cand_mask);
  scan2<<<256, 256>>>(ctx_mask, cand_mask);

  // masked v (independent of scans)
  v_kernel<<<(CB * 256) / 8, 256>>>(cand, cand_mask, WV);

  // compacted, tf32-rounded operand copies
  compact_ctx<<<ROWCAP, 192>>>(ctx);
  compact_cand<<<dim3(256, 256), 192>>>(cand);

  // K0: M = scale * WQ @ WK^T  (rounded)
  gemm_nt<<<dim3(CD / 128, CD / 128), 256, GEMM_SMEM>>>(WQ, WK, (float*)pM, CD, CD, CD, scale);

  // K1: q_c = ctx_c @ M over compacted rows (CTAs self-disable past total)
  qgemm<<<dim3(CD / 128, (CB * CL) / 128), 256, QSMEM>>>();

  // K2: fused logits -> sigmoid -> x on compacted rows/cols
  agemm<<<dim3(4, CB), 256, ASMEM>>>();

  // K3: head MLP -> y
  head_kernel<<<CB, CH>>>(W1, b1, W2, b2, out);
}

// round 4
// speedup vs baseline: 2.0682x; 1.1588x over previous
#include <cuda_runtime.h>
#include <math.h>
#include <stdint.h>

#define CB 256
#define CL 256
#define CS 253
#define CD 768
#define CH 128
#define ROWCAP (CB * CL + 128)

// ---- scratch (static device globals) ----
__device__ __align__(256) float g_MT[CD * CD];                   // (s*WQ@WK^T)^T, n-major, rounded
__device__ __align__(256) float g_ctx_c[(size_t)ROWCAP * CD];    // compacted ctx rows, rounded
__device__ __align__(256) float g_qc[(size_t)ROWCAP * CD];       // compacted q'' rows, rounded
__device__ __align__(256) float g_cand_c[(size_t)CB * 256 * CD]; // per-batch compacted cand, rounded
__device__ float g_v[CB * 256];   // v' at compacted col positions
__device__ float g_x[CB * CL];
__device__ int g_rowmap[ROWCAP];
__device__ int g_colmap[CB * 256];
__device__ int g_start[CB];
__device__ int g_cnt[CB];
__device__ int g_cnt_s[CB];
__device__ int g_total;

// =====================================================================
// helpers
// =====================================================================
__device__ __forceinline__ unsigned f2tf(float f) {
  unsigned r;
  asm("cvt.rna.tf32.f32 %0, %1;" : "=r"(r) : "f"(f));
  return r;
}
__device__ __forceinline__ float frnd(float f) { return __uint_as_float(f2tf(f)); }

__device__ __forceinline__ uint32_t smem_u32(const void* p) {
  uint32_t a;
  asm("{ .reg .u64 t; cvta.to.shared.u64 t, %1; cvt.u32.u64 %0, t; }" : "=r"(a) : "l"(p));
  return a;
}

__device__ __forceinline__ void cp16(uint32_t dst, const void* src) {
  asm volatile("cp.async.cg.shared.global [%0], [%1], 16;" ::"r"(dst), "l"(src) : "memory");
}
#define CP_COMMIT() asm volatile("cp.async.commit_group;" ::: "memory")
#define CP_WAIT1() asm volatile("cp.async.wait_group 1;" ::: "memory")

__device__ __forceinline__ void mma8(float c[4], const unsigned a[4],
                                     unsigned b0, unsigned b1) {
  asm volatile(
      "mma.sync.aligned.m16n8k8.row.col.f32.tf32.tf32.f32 "
      "{%0,%1,%2,%3}, {%4,%5,%6,%7}, {%8,%9}, {%0,%1,%2,%3};"
      : "+f"(c[0]), "+f"(c[1]), "+f"(c[2]), "+f"(c[3])
      : "r"(a[0]), "r"(a[1]), "r"(a[2]), "r"(a[3]), "r"(b0), "r"(b1));
}

#define LDSM_X4(r0, r1, r2, r3, addr)                                        \
  asm volatile("ldmatrix.sync.aligned.m8n8.x4.shared.b16 {%0,%1,%2,%3}, [%4];" \
               : "=r"(r0), "=r"(r1), "=r"(r2), "=r"(r3)                      \
               : "r"(addr))

// =====================================================================
// scan1: per-batch mask counts + global prefix over ctx counts. 1 block.
// =====================================================================
__global__ void scan1(const int* __restrict__ ctx_mask, const int* __restrict__ cand_mask) {
  __shared__ int sc[CB];
  int b = threadIdx.x;
  int c = 0;
  for (int l = 0; l < CL; l++) c += ctx_mask[b * CL + l];
  int cs = 0;
  for (int s = 0; s < CS; s++) cs += cand_mask[b * CS + s];
  g_cnt[b] = c;
  g_cnt_s[b] = cs;
  sc[b] = c;
  __syncthreads();
  for (int off = 1; off < CB; off <<= 1) {
    int v = (b >= off) ? sc[b - off] : 0;
    __syncthreads();
    sc[b] += v;
    __syncthreads();
  }
  g_start[b] = sc[b] - c;
  if (b == CB - 1) g_total = sc[b];
}

// =====================================================================
// scan2: rowmap/colmap ranks; zero g_x and g_v; sentinels.
// =====================================================================
__global__ void scan2(const int* __restrict__ ctx_mask, const int* __restrict__ cand_mask) {
  __shared__ int wsum[8], wsum2[8];
  int b = blockIdx.x, t = threadIdx.x, lane = t & 31, w = t >> 5;
  g_x[b * CL + t] = 0.f;
  g_v[b * 256 + t] = 0.f;
  g_colmap[b * 256 + t] = -1;
  int m = ctx_mask[b * CL + t];
  unsigned bal = __ballot_sync(~0u, m != 0);
  int wr = __popc(bal & ((1u << lane) - 1));
  int m2 = (t < CS) ? cand_mask[b * CS + t] : 0;
  unsigned bal2 = __ballot_sync(~0u, m2 != 0);
  int wr2 = __popc(bal2 & ((1u << lane) - 1));
  if (lane == 0) {
    wsum[w] = __popc(bal);
    wsum2[w] = __popc(bal2);
  }
  __syncthreads();
  int off = 0, off2 = 0;
  for (int i = 0; i < w; i++) {
    off += wsum[i];
    off2 += wsum2[i];
  }
  if (m) g_rowmap[g_start[b] + off + wr] = b * CL + t;
  if (m2) g_colmap[b * 256 + off2 + wr2] = t;
  if (b == 0 && t < 128) g_rowmap[g_total + t] = -1;
}

// =====================================================================
// compact_ctx: g_ctx_c[i] = rnd(ctx[rowmap[i]]) (zeros for sentinel).
// =====================================================================
__global__ void compact_ctx(const float* __restrict__ ctx) {
  int i = blockIdx.x;
  int ptot = (g_total + 127) & ~127;
  if (i >= ptot) return;
  int src = g_rowmap[i];
  int t = threadIdx.x;
  float4 v = make_float4(0.f, 0.f, 0.f, 0.f);
  if (src >= 0) v = ((const float4*)(ctx + (size_t)src * CD))[t];
  v.x = frnd(v.x); v.y = frnd(v.y); v.z = frnd(v.z); v.w = frnd(v.w);
  ((float4*)(g_ctx_c + (size_t)i * CD))[t] = v;
}

// =====================================================================
// compact_cand_v: gather+round cand row AND compute v' = dot(row, WV)
// in the same pass (one read of cand total). 192 threads/block.
// =====================================================================
__global__ void compact_cand_v(const float* __restrict__ cand,
                               const float* __restrict__ WV) {
  __shared__ float red[6];
  int b = blockIdx.y, j = blockIdx.x;
  int lim = (g_cnt_s[b] > 128) ? 256 : 128;
  if (j >= lim) return;
  int s = g_colmap[b * 256 + j];
  int t = threadIdx.x, lane = t & 31;
  float4 v = make_float4(0.f, 0.f, 0.f, 0.f);
  if (s >= 0) v = ((const float4*)(cand + ((size_t)b * CS + s) * CD))[t];
  float4 wv = ((const float4*)WV)[t];
  float p = v.x * wv.x + v.y * wv.y + v.z * wv.z + v.w * wv.w;
#pragma unroll
  for (int o = 16; o > 0; o >>= 1) p += __shfl_xor_sync(~0u, p, o);
  if (lane == 0) red[t >> 5] = p;
  v.x = frnd(v.x); v.y = frnd(v.y); v.z = frnd(v.z); v.w = frnd(v.w);
  ((float4*)(g_cand_c + ((size_t)b * 256 + j) * CD))[t] = v;
  __syncthreads();
  if (t == 0)
    g_v[b * 256 + j] = red[0] + red[1] + red[2] + red[3] + red[4] + red[5];
}

// =====================================================================
// K0: g_MT = (scale * WQ @ WK^T)^T, tf32-rounded, n-major.
// =====================================================================
__global__ void __launch_bounds__(256, 1)
gemm_nt(const float* __restrict__ A, const float* __restrict__ Bm, float cscale) {
  extern __shared__ unsigned smem_u[];
  constexpr int K = CD, N = CD;
  constexpr int ASTR = 36;
  constexpr int BSTR = 132;
  unsigned* As = smem_u;
  unsigned* Bs = smem_u + 2 * 128 * ASTR;

  const int tid = threadIdx.x;
  const int lane = tid & 31, warp = tid >> 5;
  const int wm = warp >> 1, wn = warp & 1;
  const int grp = lane >> 2, qd = lane & 3;
  const int bm = blockIdx.y, bn = blockIdx.x;

  const float* Agp = A + (size_t)bm * 128 * K;

  float acc[2][8][4];
#pragma unroll
  for (int i = 0; i < 2; i++)
#pragma unroll
    for (int j = 0; j < 8; j++)
#pragma unroll
      for (int t = 0; t < 4; t++) acc[i][j][t] = 0.f;

  float4 ra[4], rb[4];
  auto ldA = [&](int kt) {
#pragma unroll
    for (int i = 0; i < 4; i++) {
      int f = tid + i * 256, r = f >> 3, c = f & 7;
      ra[i] = *(reinterpret_cast<const float4*>(Agp + (size_t)r * K + kt * 32) + c);
    }
  };
  auto ldB = [&](int kt) {
#pragma unroll
    for (int i = 0; i < 4; i++) {
      int f = tid + i * 256, r = f >> 3, c = f & 7;
      rb[i] = *(reinterpret_cast<const float4*>(Bm + (size_t)(bn * 128 + r) * K + kt * 32) + c);
    }
  };
  auto stA = [&](int buf) {
    unsigned* ap = As + buf * 128 * ASTR;
#pragma unroll
    for (int i = 0; i < 4; i++) {
      int f = tid + i * 256, r = f >> 3, c = f & 7;
      unsigned* p = ap + r * ASTR + c * 4;
      p[0] = f2tf(ra[i].x); p[1] = f2tf(ra[i].y); p[2] = f2tf(ra[i].z); p[3] = f2tf(ra[i].w);
    }
  };
  auto stB = [&](int buf) {
    unsigned* bp = Bs + buf * 32 * BSTR;
#pragma unroll
    for (int i = 0; i < 4; i++) {
      int f = tid + i * 256, r = f >> 3, c = f & 7;
      bp[(c * 4 + 0) * BSTR + r] = f2tf(rb[i].x);
      bp[(c * 4 + 1) * BSTR + r] = f2tf(rb[i].y);
      bp[(c * 4 + 2) * BSTR + r] = f2tf(rb[i].z);
      bp[(c * 4 + 3) * BSTR + r] = f2tf(rb[i].w);
    }
  };
  auto compute = [&](int buf) {
    const unsigned* ap = As + buf * 128 * ASTR;
    const unsigned* bp = Bs + buf * 32 * BSTR;
#pragma unroll
    for (int ks = 0; ks < 4; ks++) {
      unsigned afr[2][4];
#pragma unroll
      for (int mi = 0; mi < 2; mi++) {
        int row = wm * 32 + mi * 16 + grp;
        afr[mi][0] = ap[row * ASTR + ks * 8 + qd];
        afr[mi][1] = ap[(row + 8) * ASTR + ks * 8 + qd];
        afr[mi][2] = ap[row * ASTR + ks * 8 + qd + 4];
        afr[mi][3] = ap[(row + 8) * ASTR + ks * 8 + qd + 4];
      }
#pragma unroll
      for (int ni = 0; ni < 8; ni++) {
        int col = wn * 64 + ni * 8 + grp;
        unsigned b0 = bp[(ks * 8 + qd) * BSTR + col];
        unsigned b1 = bp[(ks * 8 + qd + 4) * BSTR + col];
        mma8(acc[0][ni], afr[0], b0, b1);
        mma8(acc[1][ni], afr[1], b0, b1);
      }
    }
  };

  const int KT = K / 32;
  ldA(0); ldB(0); stA(0); stB(0);
  __syncthreads();
  for (int kt = 0; kt < KT; ++kt) {
    if (kt + 1 < KT) { ldA(kt + 1); ldB(kt + 1); }
    compute(kt & 1);
    if (kt + 1 < KT) { stA((kt + 1) & 1); stB((kt + 1) & 1); }
    __syncthreads();
  }

  // transposed store: g_MT[e][d] = C[d][e]
#pragma unroll
  for (int mi = 0; mi < 2; mi++)
#pragma unroll
    for (int ni = 0; ni < 8; ni++) {
      int r0 = bm * 128 + wm * 32 + mi * 16 + grp;
      int c0 = bn * 128 + wn * 64 + ni * 8 + qd * 2;
      g_MT[(size_t)c0 * N + r0] = frnd(acc[mi][ni][0] * cscale);
      g_MT[(size_t)(c0 + 1) * N + r0] = frnd(acc[mi][ni][1] * cscale);
      g_MT[(size_t)c0 * N + r0 + 8] = frnd(acc[mi][ni][2] * cscale);
      g_MT[(size_t)(c0 + 1) * N + r0 + 8] = frnd(acc[mi][ni][3] * cscale);
    }
}

// =====================================================================
// Unified 128x128xK=768 tf32 mainloop (ldmatrix fragments, 3-stage
// cp.async, 2 CTAs/SM). A [128][k], B [128 n-rows][k], both stride-36.
// MODE 0 (qgemm):  A = ctx_c rows, B = g_MT,    epilogue: store q''
// MODE 1 (agemm):  A = q_c rows,   B = cand_c,  epilogue: sigmoid*v -> x
// =====================================================================
template <int MODE>
__global__ void __launch_bounds__(256, 2) mm_main() {
  extern __shared__ char sm[];
  const int tid = threadIdx.x, lane = tid & 31, warp = tid >> 5;
  const int wm = warp >> 1, wn = warp & 1;
  const int grp = lane >> 2, qd = lane & 3;

  const char* Abase;
  const char* Bbase;
  int b = 0, mt = 0, nt = 0, cnt = 0, start = 0;
  if (MODE == 0) {
    int ptot = (g_total + 127) & ~127;
    if ((int)blockIdx.y * 128 >= ptot) return;
    Abase = (const char*)(g_ctx_c + (size_t)blockIdx.y * 128 * CD);
    Bbase = (const char*)(g_MT + (size_t)blockIdx.x * 128 * CD);
  } else {
    b = blockIdx.y; mt = blockIdx.x >> 1; nt = blockIdx.x & 1;
    cnt = g_cnt[b];
    int cs = g_cnt_s[b];
    if (mt * 128 >= cnt || nt * 128 >= cs) return;
    start = g_start[b];
    Abase = (const char*)(g_qc + (size_t)(start + mt * 128) * CD);
    Bbase = (const char*)(g_cand_c + ((size_t)b * 256 + nt * 128) * CD);
  }

  float* v_s = (float*)sm;          // [128]
  float* x_s = (float*)(sm + 512);  // [128]
  char* stg = sm + 1024;
  const uint32_t sb = smem_u32(stg);
  constexpr int ASZ = 128 * 144;
  constexpr int STG = 2 * ASZ;  // 36864

  if (MODE == 1 && tid < 128) {
    x_s[tid] = 0.f;
    v_s[tid] = g_v[b * 256 + nt * 128 + tid];
  }

  // ldmatrix per-lane byte offsets within a stage
  const int l7 = lane & 7, lb3 = (lane >> 3) & 1, lb4 = lane >> 4;
  const uint32_t a_base0 = (uint32_t)(((wm * 32 + l7 + lb3 * 8) * 36 + lb4 * 4) * 4);
  const uint32_t a_base1 = a_base0 + 16 * 36 * 4;
  uint32_t b_base[4];
#pragma unroll
  for (int j = 0; j < 4; j++)
    b_base[j] = (uint32_t)(((wn * 64 + j * 16 + l7 + lb4 * 8) * 36 + lb3 * 4) * 4);

  float acc[2][8][4];
#pragma unroll
  for (int i = 0; i < 2; i++)
#pragma unroll
    for (int j = 0; j < 8; j++)
#pragma unroll
      for (int t = 0; t < 4; t++) acc[i][j][t] = 0.f;

  auto issue = [&](int kt) {
    if (kt < 24) {
      int s = kt - (kt / 3) * 3;
      uint32_t ab = sb + s * STG, bb = ab + ASZ;
#pragma unroll
      for (int i = 0; i < 4; i++) {
        int f = tid + i * 256, r = f >> 3, c = f & 7;
        cp16(ab + r * 144 + c * 16, Abase + (size_t)r * 3072 + kt * 128 + c * 16);
        cp16(bb + r * 144 + c * 16, Bbase + (size_t)r * 3072 + kt * 128 + c * 16);
      }
    }
    CP_COMMIT();
  };

  issue(0);
  issue(1);
  for (int kt = 0; kt < 24; ++kt) {
    CP_WAIT1();
    __syncthreads();
    issue(kt + 2);
    const int s = kt - (kt / 3) * 3;
    const uint32_t abp = sb + s * STG;
    const uint32_t bbp = abp + ASZ;
#pragma unroll
    for (int ks = 0; ks < 4; ks++) {
      const uint32_t ka = ks * 32;
      unsigned a0[4], a1[4];
      LDSM_X4(a0[0], a0[1], a0[2], a0[3], abp + a_base0 + ka);
      LDSM_X4(a1[0], a1[1], a1[2], a1[3], abp + a_base1 + ka);
#pragma unroll
      for (int j = 0; j < 4; j++) {
        unsigned bf0, bf1, bf2, bf3;
        LDSM_X4(bf0, bf1, bf2, bf3, bbp + b_base[j] + ka);
        mma8(acc[0][2 * j], a0, bf0, bf1);
        mma8(acc[1][2 * j], a1, bf0, bf1);
        mma8(acc[0][2 * j + 1], a0, bf2, bf3);
        mma8(acc[1][2 * j + 1], a1, bf2, bf3);
      }
    }
  }

  if (MODE == 0) {
    const int i0 = blockIdx.y * 128, bn = blockIdx.x;
#pragma unroll
    for (int mi = 0; mi < 2; mi++)
#pragma unroll
      for (int ni = 0; ni < 8; ni++) {
        int r = wm * 32 + mi * 16 + grp;
        int c = bn * 128 + wn * 64 + ni * 8 + qd * 2;
        size_t o = (size_t)(i0 + r) * CD + c;
        g_qc[o] = frnd(acc[mi][ni][0]);
        g_qc[o + 1] = frnd(acc[mi][ni][1]);
        o += (size_t)8 * CD;
        g_qc[o] = frnd(acc[mi][ni][2]);
        g_qc[o + 1] = frnd(acc[mi][ni][3]);
      }
  } else {
    float xp[2][2] = {{0.f, 0.f}, {0.f, 0.f}};
#pragma unroll
    for (int mi = 0; mi < 2; mi++)
#pragma unroll
      for (int ni = 0; ni < 8; ni++) {
        int c0 = wn * 64 + ni * 8 + qd * 2;
        float va = v_s[c0], vb = v_s[c0 + 1];
        xp[mi][0] += va / (1.f + __expf(-acc[mi][ni][0])) + vb / (1.f + __expf(-acc[mi][ni][1]));
        xp[mi][1] += va / (1.f + __expf(-acc[mi][ni][2])) + vb / (1.f + __expf(-acc[mi][ni][3]));
      }
#pragma unroll
    for (int mi = 0; mi < 2; mi++)
#pragma unroll
      for (int rs = 0; rs < 2; rs++) {
        float v = xp[mi][rs];
        v += __shfl_xor_sync(0xffffffffu, v, 1);
        v += __shfl_xor_sync(0xffffffffu, v, 2);
        if (qd == 0) atomicAdd(&x_s[wm * 32 + mi * 16 + rs * 8 + grp], v);
      }
    __syncthreads();
    if (tid < 128 && mt * 128 + tid < cnt)
      atomicAdd(&g_x[g_rowmap[start + mt * 128 + tid]], x_s[tid]);
  }
}

// =====================================================================
// Head: y[b,:] = (x_b @ W1 + b1) @ W2 + b2.
// =====================================================================
__global__ void head_kernel(const float* __restrict__ W1, const float* __restrict__ b1,
                            const float* __restrict__ W2, const float* __restrict__ b2,
                            float* __restrict__ out) {
  __shared__ float xs[CL];
  __shared__ float hs[CH];
  int b = blockIdx.x, tid = threadIdx.x;
  xs[tid] = g_x[b * CL + tid];
  xs[tid + 128] = g_x[b * CL + tid + 128];
  __syncthreads();
  float h = b1[tid];
  for (int l = 0; l < CL; l++) h += xs[l] * W1[l * CH + tid];
  hs[tid] = h;
  __syncthreads();
  if (tid < 5) {
    float y = b2[tid];
    for (int k = 0; k < CH; k++) y += hs[k] * W2[k * 5 + tid];
    out[b * 5 + tid] = y;
  }
}

extern "C" void kernel_launch(void* const* d_in, const int* in_sizes, int n_in,
                              void* d_out, int out_size) {
  const float* ctx = (const float*)d_in[0];
  const float* cand = (const float*)d_in[1];
  const int* ctx_mask = (const int*)d_in[2];
  const int* cand_mask = (const int*)d_in[3];
  const float* WK = (const float*)d_in[4];
  const float* WQ = (const float*)d_in[5];
  const float* WV = (const float*)d_in[6];
  const float* W1 = (const float*)d_in[7];
  const float* b1 = (const float*)d_in[8];
  const float* W2 = (const float*)d_in[9];
  const float* b2 = (const float*)d_in[10];
  float* out = (float*)d_out;
  (void)in_sizes; (void)n_in; (void)out_size;

  constexpr int GEMM_SMEM = (2 * 128 * 36 + 2 * 32 * 132) * 4;  // 70656
  constexpr int MM_SMEM = 1024 + 3 * (2 * 128 * 144);           // 111616

  cudaFuncSetAttribute(gemm_nt, cudaFuncAttributeMaxDynamicSharedMemorySize, GEMM_SMEM);
  cudaFuncSetAttribute(mm_main<0>, cudaFuncAttributeMaxDynamicSharedMemorySize, MM_SMEM);
  cudaFuncSetAttribute(mm_main<1>, cudaFuncAttributeMaxDynamicSharedMemorySize, MM_SMEM);

  float scale = 1.0f / sqrtf((float)CD);

  // 0: mask scans
  scan1<<<1, 256>>>(ctx_mask, cand_mask);
  // 1: compaction maps + zero x/v
  scan2<<<256, 256>>>(ctx_mask, cand_mask);
  // 2: gather+round cand, fused v' dot
  compact_cand_v<<<dim3(256, 256), 192>>>(cand, WV);
  // 3: gather+round ctx rows
  compact_ctx<<<ROWCAP, 192>>>(ctx);
  // 4: K0 -> g_MT (transposed, rounded)
  gemm_nt<<<dim3(CD / 128, CD / 128), 256, GEMM_SMEM>>>(WQ, WK, scale);
  // 5 (profiled): q_c = ctx_c @ M
  mm_main<0><<<dim3(CD / 128, (CB * CL) / 128), 256, MM_SMEM>>>();
  // 6: fused logits -> sigmoid -> x
  mm_main<1><<<dim3(4, CB), 256, MM_SMEM>>>();
  // 7: head MLP -> y
  head_kernel<<<CB, CH>>>(W1, b1, W2, b2, out);
}

// round 6
// speedup vs baseline: 2.1058x; 1.0182x over previous
#include <cuda_runtime.h>
#include <math.h>
#include <stdint.h>

#define CB 256
#define CL 256
#define CS 253
#define CD 768
#define CH 128
#define ROWCAP (CB * CL + 128)

// ---- scratch (static device globals) ----
__device__ __align__(256) float g_MT[CD * CD];                   // (s*WQ@WK^T)^T, n-major, rounded
__device__ __align__(256) float g_ctx_c[(size_t)ROWCAP * CD];    // compacted ctx rows, rounded
__device__ __align__(256) float g_qc[(size_t)ROWCAP * CD];       // compacted q'' rows, rounded
__device__ __align__(256) float g_cand_c[(size_t)CB * 256 * CD]; // per-batch compacted cand, rounded
__device__ float g_v[CB * 256];   // v' at compacted col positions (0 on pads)
__device__ float g_x[CB * CL];
__device__ int g_rowmap[ROWCAP];
__device__ int g_colmap[CB * 256];
__device__ int g_start[CB];
__device__ int g_cnt[CB];
__device__ int g_cnt_s[CB];
__device__ int g_total;

// =====================================================================
// helpers
// =====================================================================
__device__ __forceinline__ unsigned f2tf(float f) {
  unsigned r;
  asm("cvt.rna.tf32.f32 %0, %1;" : "=r"(r) : "f"(f));
  return r;
}
__device__ __forceinline__ float frnd(float f) { return __uint_as_float(f2tf(f)); }
__device__ __forceinline__ float4 frnd4(float4 v) {
  v.x = frnd(v.x); v.y = frnd(v.y); v.z = frnd(v.z); v.w = frnd(v.w);
  return v;
}

__device__ __forceinline__ uint32_t smem_u32(const void* p) {
  uint32_t a;
  asm("{ .reg .u64 t; cvta.to.shared.u64 t, %1; cvt.u32.u64 %0, t; }" : "=r"(a) : "l"(p));
  return a;
}

__device__ __forceinline__ void cp16(uint32_t dst, const void* src) {
  asm volatile("cp.async.cg.shared.global [%0], [%1], 16;" ::"r"(dst), "l"(src) : "memory");
}
#define CP_COMMIT() asm volatile("cp.async.commit_group;" ::: "memory")
// 3-stage pipeline, prologue commits 2 groups, loop issues kt+2:
// must wait until <=1 group pending so stage kt is complete. (wait_group 2
// at kt=0 returns with stage 0 still in flight -> R5's rel_err 0.15.)
#define CP_WAIT1() asm volatile("cp.async.wait_group 1;" ::: "memory")

__device__ __forceinline__ void mma8(float c[4], const unsigned a[4],
                                     unsigned b0, unsigned b1) {
  asm volatile(
      "mma.sync.aligned.m16n8k8.row.col.f32.tf32.tf32.f32 "
      "{%0,%1,%2,%3}, {%4,%5,%6,%7}, {%8,%9}, {%0,%1,%2,%3};"
      : "+f"(c[0]), "+f"(c[1]), "+f"(c[2]), "+f"(c[3])
      : "r"(a[0]), "r"(a[1]), "r"(a[2]), "r"(a[3]), "r"(b0), "r"(b1));
}

#define LDSM_X4(r0, r1, r2, r3, addr)                                          \
  asm volatile("ldmatrix.sync.aligned.m8n8.x4.shared.b16 {%0,%1,%2,%3}, [%4];" \
               : "=r"(r0), "=r"(r1), "=r"(r2), "=r"(r3)                        \
               : "r"(addr))

// =====================================================================
// scan1: per-batch mask counts + global prefix over ctx counts. 1 block.
// =====================================================================
__global__ void scan1(const int* __restrict__ ctx_mask, const int* __restrict__ cand_mask) {
  __shared__ int sc[CB];
  int b = threadIdx.x;
  int c = 0;
  for (int l = 0; l < CL; l++) c += ctx_mask[b * CL + l];
  int cs = 0;
  for (int s = 0; s < CS; s++) cs += cand_mask[b * CS + s];
  g_cnt[b] = c;
  g_cnt_s[b] = cs;
  sc[b] = c;
  __syncthreads();
  for (int off = 1; off < CB; off <<= 1) {
    int v = (b >= off) ? sc[b - off] : 0;
    __syncthreads();
    sc[b] += v;
    __syncthreads();
  }
  g_start[b] = sc[b] - c;
  if (b == CB - 1) g_total = sc[b];
}

// =====================================================================
// gather: one block per batch. Builds rowmap/colmap, gathers+rounds ctx
// and cand rows into compacted buffers, computes v' = cand_c @ WV.
// No pad zero-fill needed: pad cols have v'=0 (zeroed here) so their
// logits contribute 0; pad q-rows are discarded by the agemm row guard.
// =====================================================================
__global__ void __launch_bounds__(256) gather(
    const float* __restrict__ ctx, const float* __restrict__ cand,
    const float* __restrict__ WV,
    const int* __restrict__ ctx_mask, const int* __restrict__ cand_mask) {
  __shared__ int wsum[8], wsum2[8];
  __shared__ int lrow[256], srow[256];
  const int b = blockIdx.x, t = threadIdx.x, lane = t & 31, w = t >> 5;

  g_x[b * CL + t] = 0.f;
  g_v[b * 256 + t] = 0.f;

  int m = ctx_mask[b * CL + t];
  unsigned bal = __ballot_sync(~0u, m != 0);
  int wr = __popc(bal & ((1u << lane) - 1));
  int m2 = (t < CS) ? cand_mask[b * CS + t] : 0;
  unsigned bal2 = __ballot_sync(~0u, m2 != 0);
  int wr2 = __popc(bal2 & ((1u << lane) - 1));
  if (lane == 0) {
    wsum[w] = __popc(bal);
    wsum2[w] = __popc(bal2);
  }
  __syncthreads();
  int off = 0, off2 = 0;
  for (int i = 0; i < w; i++) {
    off += wsum[i];
    off2 += wsum2[i];
  }
  const int start = g_start[b];
  if (m) {
    g_rowmap[start + off + wr] = b * CL + t;
    lrow[off + wr] = t;
  }
  if (m2) {
    g_colmap[b * 256 + off2 + wr2] = t;
    srow[off2 + wr2] = t;
  }
  const int cnt = g_cnt[b], cs = g_cnt_s[b];
  __syncthreads();

  // ctx gather (dst rows contiguous -> dst index == flattened idx)
  {
    const float4* src = (const float4*)(ctx + (size_t)b * CL * CD);
    float4* dst = (float4*)(g_ctx_c + (size_t)start * CD);
    const int tot = cnt * 192;
    for (int idx = t; idx < tot; idx += 256) {
      int r = idx / 192, c = idx - r * 192;
      dst[idx] = frnd4(src[lrow[r] * 192 + c]);
    }
  }
  // cand gather
  {
    const float4* src = (const float4*)(cand + (size_t)b * CS * CD);
    float4* dst = (float4*)(g_cand_c + (size_t)b * 256 * CD);
    const int tot = cs * 192;
    for (int idx = t; idx < tot; idx += 256) {
      int r = idx / 192, c = idx - r * 192;
      dst[idx] = frnd4(src[srow[r] * 192 + c]);
    }
  }
  __syncthreads();
  // v' from rounded rows (L2-hot): warp per row
  const float4* wv4 = (const float4*)WV;
  for (int j = w; j < cs; j += 8) {
    const float4* row = (const float4*)(g_cand_c + ((size_t)b * 256 + j) * CD);
    float p = 0.f;
#pragma unroll
    for (int k2 = 0; k2 < 6; k2++) {
      float4 x = row[lane + k2 * 32];
      float4 y = wv4[lane + k2 * 32];
      p += x.x * y.x + x.y * y.y + x.z * y.z + x.w * y.w;
    }
#pragma unroll
    for (int o = 16; o > 0; o >>= 1) p += __shfl_xor_sync(~0u, p, o);
    if (lane == 0) g_v[b * 256 + j] = p;
  }
}

// =====================================================================
// K0: g_MT = (scale * WQ @ WK^T)^T, tf32-rounded, n-major.
// =====================================================================
__global__ void __launch_bounds__(256, 1)
gemm_nt(const float* __restrict__ A, const float* __restrict__ Bm, float cscale) {
  extern __shared__ unsigned smem_u[];
  constexpr int K = CD, N = CD;
  constexpr int ASTR = 36;
  constexpr int BSTR = 132;
  unsigned* As = smem_u;
  unsigned* Bs = smem_u + 2 * 128 * ASTR;

  const int tid = threadIdx.x;
  const int lane = tid & 31, warp = tid >> 5;
  const int wm = warp >> 1, wn = warp & 1;
  const int grp = lane >> 2, qd = lane & 3;
  const int bm = blockIdx.y, bn = blockIdx.x;

  const float* Agp = A + (size_t)bm * 128 * K;

  float acc[2][8][4];
#pragma unroll
  for (int i = 0; i < 2; i++)
#pragma unroll
    for (int j = 0; j < 8; j++)
#pragma unroll
      for (int t = 0; t < 4; t++) acc[i][j][t] = 0.f;

  float4 ra[4], rb[4];
  auto ldA = [&](int kt) {
#pragma unroll
    for (int i = 0; i < 4; i++) {
      int f = tid + i * 256, r = f >> 3, c = f & 7;
      ra[i] = *(reinterpret_cast<const float4*>(Agp + (size_t)r * K + kt * 32) + c);
    }
  };
  auto ldB = [&](int kt) {
#pragma unroll
    for (int i = 0; i < 4; i++) {
      int f = tid + i * 256, r = f >> 3, c = f & 7;
      rb[i] = *(reinterpret_cast<const float4*>(Bm + (size_t)(bn * 128 + r) * K + kt * 32) + c);
    }
  };
  auto stA = [&](int buf) {
    unsigned* ap = As + buf * 128 * ASTR;
#pragma unroll
    for (int i = 0; i < 4; i++) {
      int f = tid + i * 256, r = f >> 3, c = f & 7;
      unsigned* p = ap + r * ASTR + c * 4;
      p[0] = f2tf(ra[i].x); p[1] = f2tf(ra[i].y); p[2] = f2tf(ra[i].z); p[3] = f2tf(ra[i].w);
    }
  };
  auto stB = [&](int buf) {
    unsigned* bp = Bs + buf * 32 * BSTR;
#pragma unroll
    for (int i = 0; i < 4; i++) {
      int f = tid + i * 256, r = f >> 3, c = f & 7;
      bp[(c * 4 + 0) * BSTR + r] = f2tf(rb[i].x);
      bp[(c * 4 + 1) * BSTR + r] = f2tf(rb[i].y);
      bp[(c * 4 + 2) * BSTR + r] = f2tf(rb[i].z);
      bp[(c * 4 + 3) * BSTR + r] = f2tf(rb[i].w);
    }
  };
  auto compute = [&](int buf) {
    const unsigned* ap = As + buf * 128 * ASTR;
    const unsigned* bp = Bs + buf * 32 * BSTR;
#pragma unroll
    for (int ks = 0; ks < 4; ks++) {
      unsigned afr[2][4];
#pragma unroll
      for (int mi = 0; mi < 2; mi++) {
        int row = wm * 32 + mi * 16 + grp;
        afr[mi][0] = ap[row * ASTR + ks * 8 + qd];
        afr[mi][1] = ap[(row + 8) * ASTR + ks * 8 + qd];
        afr[mi][2] = ap[row * ASTR + ks * 8 + qd + 4];
        afr[mi][3] = ap[(row + 8) * ASTR + ks * 8 + qd + 4];
      }
#pragma unroll
      for (int ni = 0; ni < 8; ni++) {
        int col = wn * 64 + ni * 8 + grp;
        unsigned b0 = bp[(ks * 8 + qd) * BSTR + col];
        unsigned b1 = bp[(ks * 8 + qd + 4) * BSTR + col];
        mma8(acc[0][ni], afr[0], b0, b1);
        mma8(acc[1][ni], afr[1], b0, b1);
      }
    }
  };

  const int KT = K / 32;
  ldA(0); ldB(0); stA(0); stB(0);
  __syncthreads();
  for (int kt = 0; kt < KT; ++kt) {
    if (kt + 1 < KT) { ldA(kt + 1); ldB(kt + 1); }
    compute(kt & 1);
    if (kt + 1 < KT) { stA((kt + 1) & 1); stB((kt + 1) & 1); }
    __syncthreads();
  }

  // transposed store: g_MT[e][d] = C[d][e]
#pragma unroll
  for (int mi = 0; mi < 2; mi++)
#pragma unroll
    for (int ni = 0; ni < 8; ni++) {
      int r0 = bm * 128 + wm * 32 + mi * 16 + grp;
      int c0 = bn * 128 + wn * 64 + ni * 8 + qd * 2;
      g_MT[(size_t)c0 * N + r0] = frnd(acc[mi][ni][0] * cscale);
      g_MT[(size_t)(c0 + 1) * N + r0] = frnd(acc[mi][ni][1] * cscale);
      g_MT[(size_t)c0 * N + r0 + 8] = frnd(acc[mi][ni][2] * cscale);
      g_MT[(size_t)(c0 + 1) * N + r0 + 8] = frnd(acc[mi][ni][3] * cscale);
    }
}

// =====================================================================
// Unified 128x128xK=768 tf32 mainloop (ldmatrix fragments, 3-stage
// cp.async (wait_group 1), 2 CTAs/SM).
// MODE 0 (qgemm):  A = ctx_c rows, B = g_MT,    epilogue: store q''
// MODE 1 (agemm):  A = q_c rows,   B = cand_c,  epilogue: sigmoid*v -> x
// =====================================================================
template <int MODE>
__global__ void __launch_bounds__(256, 2) mm_main() {
  extern __shared__ char sm[];
  const int tid = threadIdx.x, lane = tid & 31, warp = tid >> 5;
  const int wm = warp >> 1, wn = warp & 1;
  const int grp = lane >> 2, qd = lane & 3;

  const char* Abase;
  const char* Bbase;
  int b = 0, mt = 0, nt = 0, cnt = 0, start = 0;
  if (MODE == 0) {
    int ptot = (g_total + 127) & ~127;
    if ((int)blockIdx.y * 128 >= ptot) return;
    Abase = (const char*)(g_ctx_c + (size_t)blockIdx.y * 128 * CD);
    Bbase = (const char*)(g_MT + (size_t)blockIdx.x * 128 * CD);
  } else {
    b = blockIdx.y; mt = blockIdx.x >> 1; nt = blockIdx.x & 1;
    cnt = g_cnt[b];
    int cs = g_cnt_s[b];
    if (mt * 128 >= cnt || nt * 128 >= cs) return;
    start = g_start[b];
    Abase = (const char*)(g_qc + (size_t)(start + mt * 128) * CD);
    Bbase = (const char*)(g_cand_c + ((size_t)b * 256 + nt * 128) * CD);
  }

  float* v_s = (float*)sm;          // [128]
  float* x_s = (float*)(sm + 512);  // [128]
  char* stg = sm + 1024;
  const uint32_t sb = smem_u32(stg);
  constexpr int ASZ = 128 * 144;
  constexpr int STG = 2 * ASZ;  // 36864

  if (MODE == 1 && tid < 128) {
    x_s[tid] = 0.f;
    v_s[tid] = g_v[b * 256 + nt * 128 + tid];
  }

  // ldmatrix per-lane byte offsets within a stage
  const int l7 = lane & 7, lb3 = (lane >> 3) & 1, lb4 = lane >> 4;
  const uint32_t a_base0 = (uint32_t)(((wm * 32 + l7 + lb3 * 8) * 36 + lb4 * 4) * 4);
  const uint32_t a_base1 = a_base0 + 16 * 36 * 4;
  uint32_t b_base[4];
#pragma unroll
  for (int j = 0; j < 4; j++)
    b_base[j] = (uint32_t)(((wn * 64 + j * 16 + l7 + lb4 * 8) * 36 + lb3 * 4) * 4);

  float acc[2][8][4];
#pragma unroll
  for (int i = 0; i < 2; i++)
#pragma unroll
    for (int j = 0; j < 8; j++)
#pragma unroll
      for (int t = 0; t < 4; t++) acc[i][j][t] = 0.f;

  auto issue = [&](int kt) {
    if (kt < 24) {
      int s = kt - (kt / 3) * 3;
      uint32_t ab = sb + s * STG, bb = ab + ASZ;
#pragma unroll
      for (int i = 0; i < 4; i++) {
        int f = tid + i * 256, r = f >> 3, c = f & 7;
        cp16(ab + r * 144 + c * 16, Abase + (size_t)r * 3072 + kt * 128 + c * 16);
        cp16(bb + r * 144 + c * 16, Bbase + (size_t)r * 3072 + kt * 128 + c * 16);
      }
    }
    CP_COMMIT();
  };

  issue(0);
  issue(1);
  for (int kt = 0; kt < 24; ++kt) {
    CP_WAIT1();
    __syncthreads();
    issue(kt + 2);
    const int s = kt - (kt / 3) * 3;
    const uint32_t abp = sb + s * STG;
    const uint32_t bbp = abp + ASZ;
#pragma unroll
    for (int ks = 0; ks < 4; ks++) {
      const uint32_t ka = ks * 32;
      unsigned a0[4], a1[4];
      LDSM_X4(a0[0], a0[1], a0[2], a0[3], abp + a_base0 + ka);
      LDSM_X4(a1[0], a1[1], a1[2], a1[3], abp + a_base1 + ka);
#pragma unroll
      for (int j = 0; j < 4; j++) {
        unsigned bf0, bf1, bf2, bf3;
        LDSM_X4(bf0, bf1, bf2, bf3, bbp + b_base[j] + ka);
        mma8(acc[0][2 * j], a0, bf0, bf1);
        mma8(acc[1][2 * j], a1, bf0, bf1);
        mma8(acc[0][2 * j + 1], a0, bf2, bf3);
        mma8(acc[1][2 * j + 1], a1, bf2, bf3);
      }
    }
  }

  if (MODE == 0) {
    const int i0 = blockIdx.y * 128, bn = blockIdx.x;
#pragma unroll
    for (int mi = 0; mi < 2; mi++)
#pragma unroll
      for (int ni = 0; ni < 8; ni++) {
        int r = wm * 32 + mi * 16 + grp;
        int c = bn * 128 + wn * 64 + ni * 8 + qd * 2;
        size_t o = (size_t)(i0 + r) * CD + c;
        *(float2*)(g_qc + o) = make_float2(frnd(acc[mi][ni][0]), frnd(acc[mi][ni][1]));
        o += (size_t)8 * CD;
        *(float2*)(g_qc + o) = make_float2(frnd(acc[mi][ni][2]), frnd(acc[mi][ni][3]));
      }
  } else {
    float xp[2][2] = {{0.f, 0.f}, {0.f, 0.f}};
#pragma unroll
    for (int mi = 0; mi < 2; mi++)
#pragma unroll
      for (int ni = 0; ni < 8; ni++) {
        int c0 = wn * 64 + ni * 8 + qd * 2;
        float va = v_s[c0], vb = v_s[c0 + 1];
        xp[mi][0] += va / (1.f + __expf(-acc[mi][ni][0])) + vb / (1.f + __expf(-acc[mi][ni][1]));
        xp[mi][1] += va / (1.f + __expf(-acc[mi][ni][2])) + vb / (1.f + __expf(-acc[mi][ni][3]));
      }
#pragma unroll
    for (int mi = 0; mi < 2; mi++)
#pragma unroll
      for (int rs = 0; rs < 2; rs++) {
        float v = xp[mi][rs];
        v += __shfl_xor_sync(0xffffffffu, v, 1);
        v += __shfl_xor_sync(0xffffffffu, v, 2);
        if (qd == 0) atomicAdd(&x_s[wm * 32 + mi * 16 + rs * 8 + grp], v);
      }
    __syncthreads();
    if (tid < 128 && mt * 128 + tid < cnt)
      atomicAdd(&g_x[g_rowmap[start + mt * 128 + tid]], x_s[tid]);
  }
}

// =====================================================================
// Head: y[b,:] = (x_b @ W1 + b1) @ W2 + b2.
// =====================================================================
__global__ void head_kernel(const float* __restrict__ W1, const float* __restrict__ b1,
                            const float* __restrict__ W2, const float* __restrict__ b2,
                            float* __restrict__ out) {
  __shared__ float xs[CL];
  __shared__ float hs[CH];
  int b = blockIdx.x, tid = threadIdx.x;
  xs[tid] = g_x[b * CL + tid];
  xs[tid + 128] = g_x[b * CL + tid + 128];
  __syncthreads();
  float h = b1[tid];
  for (int l = 0; l < CL; l++) h += xs[l] * W1[l * CH + tid];
  hs[tid] = h;
  __syncthreads();
  if (tid < 5) {
    float y = b2[tid];
    for (int k = 0; k < CH; k++) y += hs[k] * W2[k * 5 + tid];
    out[b * 5 + tid] = y;
  }
}

extern "C" void kernel_launch(void* const* d_in, const int* in_sizes, int n_in,
                              void* d_out, int out_size) {
  const float* ctx = (const float*)d_in[0];
  const float* cand = (const float*)d_in[1];
  const int* ctx_mask = (const int*)d_in[2];
  const int* cand_mask = (const int*)d_in[3];
  const float* WK = (const float*)d_in[4];
  const float* WQ = (const float*)d_in[5];
  const float* WV = (const float*)d_in[6];
  const float* W1 = (const float*)d_in[7];
  const float* b1 = (const float*)d_in[8];
  const float* W2 = (const float*)d_in[9];
  const float* b2 = (const float*)d_in[10];
  float* out = (float*)d_out;
  (void)in_sizes; (void)n_in; (void)out_size;

  constexpr int GEMM_SMEM = (2 * 128 * 36 + 2 * 32 * 132) * 4;  // 70656
  constexpr int MM_SMEM = 1024 + 3 * (2 * 128 * 144);           // 111616

  cudaFuncSetAttribute(gemm_nt, cudaFuncAttributeMaxDynamicSharedMemorySize, GEMM_SMEM);
  cudaFuncSetAttribute(mm_main<0>, cudaFuncAttributeMaxDynamicSharedMemorySize, MM_SMEM);
  cudaFuncSetAttribute(mm_main<1>, cudaFuncAttributeMaxDynamicSharedMemorySize, MM_SMEM);

  float scale = 1.0f / sqrtf((float)CD);

  // 0: mask counts + prefix
  scan1<<<1, 256>>>(ctx_mask, cand_mask);
  // 1: fused maps + gather/round ctx & cand + v'
  gather<<<256, 256>>>(ctx, cand, WV, ctx_mask, cand_mask);
  // 2: K0 -> g_MT (transposed, rounded)
  gemm_nt<<<dim3(CD / 128, CD / 128), 256, GEMM_SMEM>>>(WQ, WK, scale);
  // 3 (profiled): q_c = ctx_c @ M
  mm_main<0><<<dim3(CD / 128, (CB * CL) / 128), 256, MM_SMEM>>>();
  // 4: fused logits -> sigmoid -> x
  mm_main<1><<<dim3(4, CB), 256, MM_SMEM>>>();
  // 5: head MLP -> y
  head_kernel<<<CB, CH>>>(W1, b1, W2, b2, out);
}

// round 7
// speedup vs baseline: 3.0100x; 1.4294x over previous
#include <cuda_runtime.h>
#include <cuda_fp16.h>
#include <math.h>
#include <stdint.h>

#define CB 256
#define CL 256
#define CS 253
#define CD 768
#define CH 128
#define ROWCAP (CB * CL + 128)

// ---- scratch (static device globals; zero-initialized at module load) ----
__device__ __align__(256) __half g_MT[CD * CD];                   // (s*WQ@WK^T)^T, n-major
__device__ __align__(256) __half g_ctx_c[(size_t)ROWCAP * CD];    // compacted ctx rows
__device__ __align__(256) __half g_qc[(size_t)ROWCAP * CD];       // compacted q'' rows
__device__ __align__(256) __half g_cand_c[(size_t)CB * 256 * CD]; // per-batch compacted cand
__device__ float g_v[CB * 256];   // v' at compacted col positions (0 on pads)
__device__ float g_x[CB * CL];
__device__ int g_rowmap[ROWCAP];
__device__ int g_colmap[CB * 256];
__device__ int g_start[CB];
__device__ int g_cnt[CB];
__device__ int g_cnt_s[CB];
__device__ int g_total;

// =====================================================================
// helpers
// =====================================================================
__device__ __forceinline__ unsigned f2tf(float f) {
  unsigned r;
  asm("cvt.rna.tf32.f32 %0, %1;" : "=r"(r) : "f"(f));
  return r;
}

__device__ __forceinline__ uint32_t smem_u32(const void* p) {
  uint32_t a;
  asm("{ .reg .u64 t; cvta.to.shared.u64 t, %1; cvt.u32.u64 %0, t; }" : "=r"(a) : "l"(p));
  return a;
}

__device__ __forceinline__ void cp16(uint32_t dst, const void* src) {
  asm volatile("cp.async.cg.shared.global [%0], [%1], 16;" ::"r"(dst), "l"(src) : "memory");
}
#define CP_COMMIT() asm volatile("cp.async.commit_group;" ::: "memory")
// 3-stage pipeline, prologue commits 2 groups, loop issues kt+2:
// wait until <=1 pending so stage kt is complete (R5 lesson: NOT 2).
#define CP_WAIT1() asm volatile("cp.async.wait_group 1;" ::: "memory")

// legacy tf32 mma for the tiny K0 (fp32 inputs)
__device__ __forceinline__ void mma8(float c[4], const unsigned a[4],
                                     unsigned b0, unsigned b1) {
  asm volatile(
      "mma.sync.aligned.m16n8k8.row.col.f32.tf32.tf32.f32 "
      "{%0,%1,%2,%3}, {%4,%5,%6,%7}, {%8,%9}, {%0,%1,%2,%3};"
      : "+f"(c[0]), "+f"(c[1]), "+f"(c[2]), "+f"(c[3])
      : "r"(a[0]), "r"(a[1]), "r"(a[2]), "r"(a[3]), "r"(b0), "r"(b1));
}

// fp16 mma, fp32 accumulate
__device__ __forceinline__ void mma16(float c[4], const unsigned a[4],
                                      unsigned b0, unsigned b1) {
  asm volatile(
      "mma.sync.aligned.m16n8k16.row.col.f32.f16.f16.f32 "
      "{%0,%1,%2,%3}, {%4,%5,%6,%7}, {%8,%9}, {%0,%1,%2,%3};"
      : "+f"(c[0]), "+f"(c[1]), "+f"(c[2]), "+f"(c[3])
      : "r"(a[0]), "r"(a[1]), "r"(a[2]), "r"(a[3]), "r"(b0), "r"(b1));
}

#define LDSM_X4(r0, r1, r2, r3, addr)                                          \
  asm volatile("ldmatrix.sync.aligned.m8n8.x4.shared.b16 {%0,%1,%2,%3}, [%4];" \
               : "=r"(r0), "=r"(r1), "=r"(r2), "=r"(r3)                        \
               : "r"(addr))

__device__ __forceinline__ uint32_t pack2h(float a, float b) {
  __half2 h = __floats2half2_rn(a, b);
  return *(uint32_t*)&h;
}

// =====================================================================
// scan1: per-batch mask counts + global prefix over ctx counts. 1 block.
// =====================================================================
__global__ void scan1(const int* __restrict__ ctx_mask, const int* __restrict__ cand_mask) {
  __shared__ int sc[CB];
  int b = threadIdx.x;
  int c = 0;
  for (int l = 0; l < CL; l++) c += ctx_mask[b * CL + l];
  int cs = 0;
  for (int s = 0; s < CS; s++) cs += cand_mask[b * CS + s];
  g_cnt[b] = c;
  g_cnt_s[b] = cs;
  sc[b] = c;
  __syncthreads();
  for (int off = 1; off < CB; off <<= 1) {
    int v = (b >= off) ? sc[b - off] : 0;
    __syncthreads();
    sc[b] += v;
    __syncthreads();
  }
  g_start[b] = sc[b] - c;
  if (b == CB - 1) g_total = sc[b];
}

// =====================================================================
// gather: one block per batch. Builds rowmap/colmap, gathers+converts
// ctx/cand rows to fp16 compacted buffers, computes v' from the RAW
// float cand rows (no rounding error on v').
// Pads need no zero-fill: never-written rows are 0 from module load
// (deterministic across replays), pad cols have v'=0, pad q-rows are
// discarded by the agemm row guard.
// =====================================================================
__global__ void __launch_bounds__(256) gather(
    const float* __restrict__ ctx, const float* __restrict__ cand,
    const float* __restrict__ WV,
    const int* __restrict__ ctx_mask, const int* __restrict__ cand_mask) {
  __shared__ int wsum[8], wsum2[8];
  __shared__ int lrow[256], srow[256];
  const int b = blockIdx.x, t = threadIdx.x, lane = t & 31, w = t >> 5;

  g_x[b * CL + t] = 0.f;
  g_v[b * 256 + t] = 0.f;

  int m = ctx_mask[b * CL + t];
  unsigned bal = __ballot_sync(~0u, m != 0);
  int wr = __popc(bal & ((1u << lane) - 1));
  int m2 = (t < CS) ? cand_mask[b * CS + t] : 0;
  unsigned bal2 = __ballot_sync(~0u, m2 != 0);
  int wr2 = __popc(bal2 & ((1u << lane) - 1));
  if (lane == 0) {
    wsum[w] = __popc(bal);
    wsum2[w] = __popc(bal2);
  }
  __syncthreads();
  int off = 0, off2 = 0;
  for (int i = 0; i < w; i++) {
    off += wsum[i];
    off2 += wsum2[i];
  }
  const int start = g_start[b];
  if (m) {
    g_rowmap[start + off + wr] = b * CL + t;
    lrow[off + wr] = t;
  }
  if (m2) {
    g_colmap[b * 256 + off2 + wr2] = t;
    srow[off2 + wr2] = t;
  }
  const int cnt = g_cnt[b], cs = g_cnt_s[b];
  __syncthreads();

  // ctx gather -> fp16 (dst rows contiguous)
  {
    const float4* src = (const float4*)(ctx + (size_t)b * CL * CD);
    uint2* dst = (uint2*)(g_ctx_c + (size_t)start * CD);
    const int tot = cnt * 192;
    for (int idx = t; idx < tot; idx += 256) {
      int r = idx / 192, c = idx - r * 192;
      float4 v = src[lrow[r] * 192 + c];
      dst[idx] = make_uint2(pack2h(v.x, v.y), pack2h(v.z, v.w));
    }
  }
  // cand gather -> fp16
  {
    const float4* src = (const float4*)(cand + (size_t)b * CS * CD);
    uint2* dst = (uint2*)(g_cand_c + (size_t)b * 256 * CD);
    const int tot = cs * 192;
    for (int idx = t; idx < tot; idx += 256) {
      int r = idx / 192, c = idx - r * 192;
      float4 v = src[srow[r] * 192 + c];
      dst[idx] = make_uint2(pack2h(v.x, v.y), pack2h(v.z, v.w));
    }
  }
  __syncthreads();
  // v' from RAW float rows (L2-hot): warp per compacted col
  const float4* wv4 = (const float4*)WV;
  for (int j = w; j < cs; j += 8) {
    const float4* row = (const float4*)(cand + ((size_t)b * CS + srow[j]) * CD);
    float p = 0.f;
#pragma unroll
    for (int k2 = 0; k2 < 6; k2++) {
      float4 x = row[lane + k2 * 32];
      float4 y = wv4[lane + k2 * 32];
      p += x.x * y.x + x.y * y.y + x.z * y.z + x.w * y.w;
    }
#pragma unroll
    for (int o = 16; o > 0; o >>= 1) p += __shfl_xor_sync(~0u, p, o);
    if (lane == 0) g_v[b * 256 + j] = p;
  }
}

// =====================================================================
// K0: g_MT = (scale * WQ @ WK^T)^T, n-major, fp16. tf32 mma (fp32 in).
// =====================================================================
__global__ void __launch_bounds__(256, 1)
gemm_nt(const float* __restrict__ A, const float* __restrict__ Bm, float cscale) {
  extern __shared__ unsigned smem_u[];
  constexpr int K = CD, N = CD;
  constexpr int ASTR = 36;
  constexpr int BSTR = 132;
  unsigned* As = smem_u;
  unsigned* Bs = smem_u + 2 * 128 * ASTR;

  const int tid = threadIdx.x;
  const int lane = tid & 31, warp = tid >> 5;
  const int wm = warp >> 1, wn = warp & 1;
  const int grp = lane >> 2, qd = lane & 3;
  const int bm = blockIdx.y, bn = blockIdx.x;

  const float* Agp = A + (size_t)bm * 128 * K;

  float acc[2][8][4];
#pragma unroll
  for (int i = 0; i < 2; i++)
#pragma unroll
    for (int j = 0; j < 8; j++)
#pragma unroll
      for (int t = 0; t < 4; t++) acc[i][j][t] = 0.f;

  float4 ra[4], rb[4];
  auto ldA = [&](int kt) {
#pragma unroll
    for (int i = 0; i < 4; i++) {
      int f = tid + i * 256, r = f >> 3, c = f & 7;
      ra[i] = *(reinterpret_cast<const float4*>(Agp + (size_t)r * K + kt * 32) + c);
    }
  };
  auto ldB = [&](int kt) {
#pragma unroll
    for (int i = 0; i < 4; i++) {
      int f = tid + i * 256, r = f >> 3, c = f & 7;
      rb[i] = *(reinterpret_cast<const float4*>(Bm + (size_t)(bn * 128 + r) * K + kt * 32) + c);
    }
  };
  auto stA = [&](int buf) {
    unsigned* ap = As + buf * 128 * ASTR;
#pragma unroll
    for (int i = 0; i < 4; i++) {
      int f = tid + i * 256, r = f >> 3, c = f & 7;
      unsigned* p = ap + r * ASTR + c * 4;
      p[0] = f2tf(ra[i].x); p[1] = f2tf(ra[i].y); p[2] = f2tf(ra[i].z); p[3] = f2tf(ra[i].w);
    }
  };
  auto stB = [&](int buf) {
    unsigned* bp = Bs + buf * 32 * BSTR;
#pragma unroll
    for (int i = 0; i < 4; i++) {
      int f = tid + i * 256, r = f >> 3, c = f & 7;
      bp[(c * 4 + 0) * BSTR + r] = f2tf(rb[i].x);
      bp[(c * 4 + 1) * BSTR + r] = f2tf(rb[i].y);
      bp[(c * 4 + 2) * BSTR + r] = f2tf(rb[i].z);
      bp[(c * 4 + 3) * BSTR + r] = f2tf(rb[i].w);
    }
  };
  auto compute = [&](int buf) {
    const unsigned* ap = As + buf * 128 * ASTR;
    const unsigned* bp = Bs + buf * 32 * BSTR;
#pragma unroll
    for (int ks = 0; ks < 4; ks++) {
      unsigned afr[2][4];
#pragma unroll
      for (int mi = 0; mi < 2; mi++) {
        int row = wm * 32 + mi * 16 + grp;
        afr[mi][0] = ap[row * ASTR + ks * 8 + qd];
        afr[mi][1] = ap[(row + 8) * ASTR + ks * 8 + qd];
        afr[mi][2] = ap[row * ASTR + ks * 8 + qd + 4];
        afr[mi][3] = ap[(row + 8) * ASTR + ks * 8 + qd + 4];
      }
#pragma unroll
      for (int ni = 0; ni < 8; ni++) {
        int col = wn * 64 + ni * 8 + grp;
        unsigned b0 = bp[(ks * 8 + qd) * BSTR + col];
        unsigned b1 = bp[(ks * 8 + qd + 4) * BSTR + col];
        mma8(acc[0][ni], afr[0], b0, b1);
        mma8(acc[1][ni], afr[1], b0, b1);
      }
    }
  };

  const int KT = K / 32;
  ldA(0); ldB(0); stA(0); stB(0);
  __syncthreads();
  for (int kt = 0; kt < KT; ++kt) {
    if (kt + 1 < KT) { ldA(kt + 1); ldB(kt + 1); }
    compute(kt & 1);
    if (kt + 1 < KT) { stA((kt + 1) & 1); stB((kt + 1) & 1); }
    __syncthreads();
  }

  // transposed fp16 store: g_MT[e][d] = C[d][e]
#pragma unroll
  for (int mi = 0; mi < 2; mi++)
#pragma unroll
    for (int ni = 0; ni < 8; ni++) {
      int r0 = bm * 128 + wm * 32 + mi * 16 + grp;
      int c0 = bn * 128 + wn * 64 + ni * 8 + qd * 2;
      g_MT[(size_t)c0 * N + r0] = __float2half(acc[mi][ni][0] * cscale);
      g_MT[(size_t)(c0 + 1) * N + r0] = __float2half(acc[mi][ni][1] * cscale);
      g_MT[(size_t)c0 * N + r0 + 8] = __float2half(acc[mi][ni][2] * cscale);
      g_MT[(size_t)(c0 + 1) * N + r0 + 8] = __float2half(acc[mi][ni][3] * cscale);
    }
}

// =====================================================================
// Unified 128x128xK=768 fp16 mainloop: m16n8k16, ldmatrix b16 fragments,
// 3-stage cp.async (k-chunk 64 halves = 128B/row/stage), 2 CTAs/SM.
// MODE 0 (qgemm):  A = ctx_c rows, B = g_MT,    epilogue: store q'' fp16
// MODE 1 (agemm):  A = q_c rows,   B = cand_c,  epilogue: sigmoid*v -> x
// =====================================================================
template <int MODE>
__global__ void __launch_bounds__(256, 2) mm_main() {
  extern __shared__ char sm[];
  const int tid = threadIdx.x, lane = tid & 31, warp = tid >> 5;
  const int wm = warp >> 1, wn = warp & 1;
  const int grp = lane >> 2, qd = lane & 3;

  const char* Abase;
  const char* Bbase;
  int b = 0, mt = 0, nt = 0, cnt = 0, start = 0;
  if (MODE == 0) {
    int ptot = (g_total + 127) & ~127;
    if ((int)blockIdx.y * 128 >= ptot) return;
    Abase = (const char*)(g_ctx_c + (size_t)blockIdx.y * 128 * CD);
    Bbase = (const char*)(g_MT + (size_t)blockIdx.x * 128 * CD);
  } else {
    b = blockIdx.y; mt = blockIdx.x >> 1; nt = blockIdx.x & 1;
    cnt = g_cnt[b];
    int cs = g_cnt_s[b];
    if (mt * 128 >= cnt || nt * 128 >= cs) return;
    start = g_start[b];
    Abase = (const char*)(g_qc + (size_t)(start + mt * 128) * CD);
    Bbase = (const char*)(g_cand_c + ((size_t)b * 256 + nt * 128) * CD);
  }

  float* v_s = (float*)sm;          // [128]
  float* x_s = (float*)(sm + 512);  // [128]
  char* stg = sm + 1024;
  const uint32_t sb = smem_u32(stg);
  constexpr int RSTR = 144;          // 64 halves (128B) + 16B pad, conflict-free
  constexpr int ASZ = 128 * RSTR;    // 18432
  constexpr int STG = 2 * ASZ;       // 36864
  constexpr int KT = CD / 64;        // 12 k-tiles

  if (MODE == 1 && tid < 128) {
    x_s[tid] = 0.f;
    v_s[tid] = g_v[b * 256 + nt * 128 + tid];
  }

  // ldmatrix per-lane byte offsets (fp16 m16n8k16 canonical x4 pattern)
  const int l7 = lane & 7, lb3 = (lane >> 3) & 1, lb4 = lane >> 4;
  // A: r0/r1 = rows 0-7/8-15 k0-7, r2/r3 = same rows k8-15
  const uint32_t a_base0 = (uint32_t)((wm * 32 + l7 + lb3 * 8) * RSTR + lb4 * 16);
  const uint32_t a_base1 = a_base0 + 16 * RSTR;
  // B: r0/r1 = cols j16+0-7 k0-7/k8-15, r2/r3 = cols j16+8-15 k0-7/k8-15
  uint32_t b_base[4];
#pragma unroll
  for (int j = 0; j < 4; j++)
    b_base[j] = (uint32_t)((wn * 64 + j * 16 + l7 + lb4 * 8) * RSTR + lb3 * 16);

  float acc[2][8][4];
#pragma unroll
  for (int i = 0; i < 2; i++)
#pragma unroll
    for (int j = 0; j < 8; j++)
#pragma unroll
      for (int t = 0; t < 4; t++) acc[i][j][t] = 0.f;

  auto issue = [&](int kt) {
    if (kt < KT) {
      int s = kt - (kt / 3) * 3;
      uint32_t ab = sb + s * STG, bb = ab + ASZ;
#pragma unroll
      for (int i = 0; i < 4; i++) {
        int f = tid + i * 256, r = f >> 3, c = f & 7;
        cp16(ab + r * RSTR + c * 16, Abase + (size_t)r * 1536 + kt * 128 + c * 16);
        cp16(bb + r * RSTR + c * 16, Bbase + (size_t)r * 1536 + kt * 128 + c * 16);
      }
    }
    CP_COMMIT();
  };

  issue(0);
  issue(1);
  for (int kt = 0; kt < KT; ++kt) {
    CP_WAIT1();
    __syncthreads();
    issue(kt + 2);
    const int s = kt - (kt / 3) * 3;
    const uint32_t abp = sb + s * STG;
    const uint32_t bbp = abp + ASZ;
#pragma unroll
    for (int ks = 0; ks < 4; ks++) {
      const uint32_t ka = ks * 32;  // k16 = 32 bytes
      unsigned a0[4], a1[4];
      LDSM_X4(a0[0], a0[1], a0[2], a0[3], abp + a_base0 + ka);
      LDSM_X4(a1[0], a1[1], a1[2], a1[3], abp + a_base1 + ka);
#pragma unroll
      for (int j = 0; j < 4; j++) {
        unsigned bf0, bf1, bf2, bf3;
        LDSM_X4(bf0, bf1, bf2, bf3, bbp + b_base[j] + ka);
        mma16(acc[0][2 * j], a0, bf0, bf1);
        mma16(acc[1][2 * j], a1, bf0, bf1);
        mma16(acc[0][2 * j + 1], a0, bf2, bf3);
        mma16(acc[1][2 * j + 1], a1, bf2, bf3);
      }
    }
  }

  if (MODE == 0) {
    const int i0 = blockIdx.y * 128, bn = blockIdx.x;
#pragma unroll
    for (int mi = 0; mi < 2; mi++)
#pragma unroll
      for (int ni = 0; ni < 8; ni++) {
        int r = wm * 32 + mi * 16 + grp;
        int c = bn * 128 + wn * 64 + ni * 8 + qd * 2;
        size_t o = (size_t)(i0 + r) * CD + c;
        *(uint32_t*)(g_qc + o) = pack2h(acc[mi][ni][0], acc[mi][ni][1]);
        o += (size_t)8 * CD;
        *(uint32_t*)(g_qc + o) = pack2h(acc[mi][ni][2], acc[mi][ni][3]);
      }
  } else {
    float xp[2][2] = {{0.f, 0.f}, {0.f, 0.f}};
#pragma unroll
    for (int mi = 0; mi < 2; mi++)
#pragma unroll
      for (int ni = 0; ni < 8; ni++) {
        int c0 = wn * 64 + ni * 8 + qd * 2;
        float va = v_s[c0], vb = v_s[c0 + 1];
        xp[mi][0] += va / (1.f + __expf(-acc[mi][ni][0])) + vb / (1.f + __expf(-acc[mi][ni][1]));
        xp[mi][1] += va / (1.f + __expf(-acc[mi][ni][2])) + vb / (1.f + __expf(-acc[mi][ni][3]));
      }
#pragma unroll
    for (int mi = 0; mi < 2; mi++)
#pragma unroll
      for (int rs = 0; rs < 2; rs++) {
        float v = xp[mi][rs];
        v += __shfl_xor_sync(0xffffffffu, v, 1);
        v += __shfl_xor_sync(0xffffffffu, v, 2);
        if (qd == 0) atomicAdd(&x_s[wm * 32 + mi * 16 + rs * 8 + grp], v);
      }
    __syncthreads();
    if (tid < 128 && mt * 128 + tid < cnt)
      atomicAdd(&g_x[g_rowmap[start + mt * 128 + tid]], x_s[tid]);
  }
}

// =====================================================================
// Head: y[b,:] = (x_b @ W1 + b1) @ W2 + b2.
// =====================================================================
__global__ void head_kernel(const float* __restrict__ W1, const float* __restrict__ b1,
                            const float* __restrict__ W2, const float* __restrict__ b2,
                            float* __restrict__ out) {
  __shared__ float xs[CL];
  __shared__ float hs[CH];
  int b = blockIdx.x, tid = threadIdx.x;
  xs[tid] = g_x[b * CL + tid];
  xs[tid + 128] = g_x[b * CL + tid + 128];
  __syncthreads();
  float h = b1[tid];
  for (int l = 0; l < CL; l++) h += xs[l] * W1[l * CH + tid];
  hs[tid] = h;
  __syncthreads();
  if (tid < 5) {
    float y = b2[tid];
    for (int k = 0; k < CH; k++) y += hs[k] * W2[k * 5 + tid];
    out[b * 5 + tid] = y;
  }
}

extern "C" void kernel_launch(void* const* d_in, const int* in_sizes, int n_in,
                              void* d_out, int out_size) {
  const float* ctx = (const float*)d_in[0];
  const float* cand = (const float*)d_in[1];
  const int* ctx_mask = (const int*)d_in[2];
  const int* cand_mask = (const int*)d_in[3];
  const float* WK = (const float*)d_in[4];
  const float* WQ = (const float*)d_in[5];
  const float* WV = (const float*)d_in[6];
  const float* W1 = (const float*)d_in[7];
  const float* b1 = (const float*)d_in[8];
  const float* W2 = (const float*)d_in[9];
  const float* b2 = (const float*)d_in[10];
  float* out = (float*)d_out;
  (void)in_sizes; (void)n_in; (void)out_size;

  constexpr int GEMM_SMEM = (2 * 128 * 36 + 2 * 32 * 132) * 4;  // 70656
  constexpr int MM_SMEM = 1024 + 3 * (2 * 128 * 144);           // 111616

  cudaFuncSetAttribute(gemm_nt, cudaFuncAttributeMaxDynamicSharedMemorySize, GEMM_SMEM);
  cudaFuncSetAttribute(mm_main<0>, cudaFuncAttributeMaxDynamicSharedMemorySize, MM_SMEM);
  cudaFuncSetAttribute(mm_main<1>, cudaFuncAttributeMaxDynamicSharedMemorySize, MM_SMEM);

  float scale = 1.0f / sqrtf((float)CD);

  // 0: mask counts + prefix
  scan1<<<1, 256>>>(ctx_mask, cand_mask);
  // 1: fused maps + gather/convert ctx & cand + v' (raw-float dot)
  gather<<<256, 256>>>(ctx, cand, WV, ctx_mask, cand_mask);
  // 2: K0 -> g_MT (transposed, fp16)
  gemm_nt<<<dim3(CD / 128, CD / 128), 256, GEMM_SMEM>>>(WQ, WK, scale);
  // 3 (profiled): q_c = ctx_c @ M  (fp16 mainloop)
  mm_main<0><<<dim3(CD / 128, (CB * CL) / 128), 256, MM_SMEM>>>();
  // 4: fused logits -> sigmoid -> x  (fp16 mainloop)
  mm_main<1><<<dim3(4, CB), 256, MM_SMEM>>>();
  // 5: head MLP -> y
  head_kernel<<<CB, CH>>>(W1, b1, W2, b2, out);
}

// round 8
// speedup vs baseline: 3.3023x; 1.0971x over previous
#include <cuda_runtime.h>
#include <cuda_fp16.h>
#include <math.h>
#include <stdint.h>

#define CB 256
#define CL 256
#define CS 253
#define CD 768
#define CH 128
#define ROWCAP (CB * CL + 128)

// ---- scratch (static device globals; zero-initialized at module load) ----
__device__ __align__(256) __half g_MT[CD * CD];                   // (s*WQ@WK^T)^T, n-major
__device__ __align__(256) __half g_ctx_c[(size_t)ROWCAP * CD];    // compacted ctx rows
__device__ __align__(256) __half g_qc[(size_t)ROWCAP * CD];       // compacted q'' rows
__device__ __align__(256) __half g_cand_c[(size_t)CB * 256 * CD]; // per-batch compacted cand
__device__ float g_v[CB * 256];   // v' at compacted col positions (0 on pads)
__device__ float g_x[CB * CL];
__device__ int g_rowmap[ROWCAP];
__device__ int g_colmap[CB * 256];
__device__ int g_start[CB];
__device__ int g_cnt[CB];
__device__ int g_cnt_s[CB];
__device__ int g_total;

// =====================================================================
// helpers
// =====================================================================
__device__ __forceinline__ unsigned f2tf(float f) {
  unsigned r;
  asm("cvt.rna.tf32.f32 %0, %1;" : "=r"(r) : "f"(f));
  return r;
}

__device__ __forceinline__ uint32_t smem_u32(const void* p) {
  uint32_t a;
  asm("{ .reg .u64 t; cvta.to.shared.u64 t, %1; cvt.u32.u64 %0, t; }" : "=r"(a) : "l"(p));
  return a;
}

__device__ __forceinline__ void cp16(uint32_t dst, const void* src) {
  asm volatile("cp.async.cg.shared.global [%0], [%1], 16;" ::"r"(dst), "l"(src) : "memory");
}
#define CP_COMMIT() asm volatile("cp.async.commit_group;" ::: "memory")
// 3-stage pipeline, prologue commits 2 groups, loop issues kt+2:
// wait until <=1 pending so stage kt is complete (R5 lesson: NOT 2).
#define CP_WAIT1() asm volatile("cp.async.wait_group 1;" ::: "memory")

// legacy tf32 mma for the tiny K0 (fp32 inputs)
__device__ __forceinline__ void mma8(float c[4], const unsigned a[4],
                                     unsigned b0, unsigned b1) {
  asm volatile(
      "mma.sync.aligned.m16n8k8.row.col.f32.tf32.tf32.f32 "
      "{%0,%1,%2,%3}, {%4,%5,%6,%7}, {%8,%9}, {%0,%1,%2,%3};"
      : "+f"(c[0]), "+f"(c[1]), "+f"(c[2]), "+f"(c[3])
      : "r"(a[0]), "r"(a[1]), "r"(a[2]), "r"(a[3]), "r"(b0), "r"(b1));
}

// fp16 mma, fp32 accumulate
__device__ __forceinline__ void mma16(float c[4], const unsigned a[4],
                                      unsigned b0, unsigned b1) {
  asm volatile(
      "mma.sync.aligned.m16n8k16.row.col.f32.f16.f16.f32 "
      "{%0,%1,%2,%3}, {%4,%5,%6,%7}, {%8,%9}, {%0,%1,%2,%3};"
      : "+f"(c[0]), "+f"(c[1]), "+f"(c[2]), "+f"(c[3])
      : "r"(a[0]), "r"(a[1]), "r"(a[2]), "r"(a[3]), "r"(b0), "r"(b1));
}

#define LDSM_X4(r0, r1, r2, r3, addr)                                          \
  asm volatile("ldmatrix.sync.aligned.m8n8.x4.shared.b16 {%0,%1,%2,%3}, [%4];" \
               : "=r"(r0), "=r"(r1), "=r"(r2), "=r"(r3)                        \
               : "r"(addr))

__device__ __forceinline__ uint32_t pack2h(float a, float b) {
  __half2 h = __floats2half2_rn(a, b);
  return *(uint32_t*)&h;
}

// =====================================================================
// scan1: per-batch mask counts + global prefix over ctx counts. 1 block.
// =====================================================================
__global__ void scan1(const int* __restrict__ ctx_mask, const int* __restrict__ cand_mask) {
  __shared__ int sc[CB];
  int b = threadIdx.x;
  int c = 0;
  for (int l = 0; l < CL; l++) c += ctx_mask[b * CL + l];
  int cs = 0;
  for (int s = 0; s < CS; s++) cs += cand_mask[b * CS + s];
  g_cnt[b] = c;
  g_cnt_s[b] = cs;
  sc[b] = c;
  __syncthreads();
  for (int off = 1; off < CB; off <<= 1) {
    int v = (b >= off) ? sc[b - off] : 0;
    __syncthreads();
    sc[b] += v;
    __syncthreads();
  }
  g_start[b] = sc[b] - c;
  if (b == CB - 1) g_total = sc[b];
}

// =====================================================================
// fusedA: heterogeneous kernel, one wave.
//  blocks [0,256):  per-batch compaction maps + zero g_x/g_v (needs scan1)
//  blocks [256,292): K0 tiles: g_MT = (scale*WQ@WK^T)^T fp16 (independent)
// The map pass hides entirely under K0's ~25us.
// =====================================================================
__global__ void __launch_bounds__(256, 1) fusedA(
    const float* __restrict__ WQ, const float* __restrict__ WKm, float cscale,
    const int* __restrict__ ctx_mask, const int* __restrict__ cand_mask) {
  extern __shared__ unsigned smem_u[];

  if (blockIdx.x < 256) {
    __shared__ int wsum[8], wsum2[8];
    const int b = blockIdx.x, t = threadIdx.x, lane = t & 31, w = t >> 5;
    g_x[b * CL + t] = 0.f;
    g_v[b * 256 + t] = 0.f;
    int m = ctx_mask[b * CL + t];
    unsigned bal = __ballot_sync(~0u, m != 0);
    int wr = __popc(bal & ((1u << lane) - 1));
    int m2 = (t < CS) ? cand_mask[b * CS + t] : 0;
    unsigned bal2 = __ballot_sync(~0u, m2 != 0);
    int wr2 = __popc(bal2 & ((1u << lane) - 1));
    if (lane == 0) {
      wsum[w] = __popc(bal);
      wsum2[w] = __popc(bal2);
    }
    __syncthreads();
    int off = 0, off2 = 0;
    for (int i = 0; i < w; i++) {
      off += wsum[i];
      off2 += wsum2[i];
    }
    if (m) g_rowmap[g_start[b] + off + wr] = b * CL + t;
    if (m2) g_colmap[b * 256 + off2 + wr2] = t;
    return;
  }

  // ---- K0 tile ----
  constexpr int K = CD, N = CD;
  constexpr int ASTR = 36;
  constexpr int BSTR = 132;
  unsigned* As = smem_u;
  unsigned* Bs = smem_u + 2 * 128 * ASTR;

  const int tileid = blockIdx.x - 256;
  const int bm = tileid / 6, bn = tileid % 6;
  const int tid = threadIdx.x;
  const int lane = tid & 31, warp = tid >> 5;
  const int wm = warp >> 1, wn = warp & 1;
  const int grp = lane >> 2, qd = lane & 3;

  const float* Agp = WQ + (size_t)bm * 128 * K;

  float acc[2][8][4];
#pragma unroll
  for (int i = 0; i < 2; i++)
#pragma unroll
    for (int j = 0; j < 8; j++)
#pragma unroll
      for (int t = 0; t < 4; t++) acc[i][j][t] = 0.f;

  float4 ra[4], rb[4];
  auto ldA = [&](int kt) {
#pragma unroll
    for (int i = 0; i < 4; i++) {
      int f = tid + i * 256, r = f >> 3, c = f & 7;
      ra[i] = *(reinterpret_cast<const float4*>(Agp + (size_t)r * K + kt * 32) + c);
    }
  };
  auto ldB = [&](int kt) {
#pragma unroll
    for (int i = 0; i < 4; i++) {
      int f = tid + i * 256, r = f >> 3, c = f & 7;
      rb[i] = *(reinterpret_cast<const float4*>(WKm + (size_t)(bn * 128 + r) * K + kt * 32) + c);
    }
  };
  auto stA = [&](int buf) {
    unsigned* ap = As + buf * 128 * ASTR;
#pragma unroll
    for (int i = 0; i < 4; i++) {
      int f = tid + i * 256, r = f >> 3, c = f & 7;
      unsigned* p = ap + r * ASTR + c * 4;
      p[0] = f2tf(ra[i].x); p[1] = f2tf(ra[i].y); p[2] = f2tf(ra[i].z); p[3] = f2tf(ra[i].w);
    }
  };
  auto stB = [&](int buf) {
    unsigned* bp = Bs + buf * 32 * BSTR;
#pragma unroll
    for (int i = 0; i < 4; i++) {
      int f = tid + i * 256, r = f >> 3, c = f & 7;
      bp[(c * 4 + 0) * BSTR + r] = f2tf(rb[i].x);
      bp[(c * 4 + 1) * BSTR + r] = f2tf(rb[i].y);
      bp[(c * 4 + 2) * BSTR + r] = f2tf(rb[i].z);
      bp[(c * 4 + 3) * BSTR + r] = f2tf(rb[i].w);
    }
  };
  auto compute = [&](int buf) {
    const unsigned* ap = As + buf * 128 * ASTR;
    const unsigned* bp = Bs + buf * 32 * BSTR;
#pragma unroll
    for (int ks = 0; ks < 4; ks++) {
      unsigned afr[2][4];
#pragma unroll
      for (int mi = 0; mi < 2; mi++) {
        int row = wm * 32 + mi * 16 + grp;
        afr[mi][0] = ap[row * ASTR + ks * 8 + qd];
        afr[mi][1] = ap[(row + 8) * ASTR + ks * 8 + qd];
        afr[mi][2] = ap[row * ASTR + ks * 8 + qd + 4];
        afr[mi][3] = ap[(row + 8) * ASTR + ks * 8 + qd + 4];
      }
#pragma unroll
      for (int ni = 0; ni < 8; ni++) {
        int col = wn * 64 + ni * 8 + grp;
        unsigned b0 = bp[(ks * 8 + qd) * BSTR + col];
        unsigned b1 = bp[(ks * 8 + qd + 4) * BSTR + col];
        mma8(acc[0][ni], afr[0], b0, b1);
        mma8(acc[1][ni], afr[1], b0, b1);
      }
    }
  };

  const int KT = K / 32;
  ldA(0); ldB(0); stA(0); stB(0);
  __syncthreads();
  for (int kt = 0; kt < KT; ++kt) {
    if (kt + 1 < KT) { ldA(kt + 1); ldB(kt + 1); }
    compute(kt & 1);
    if (kt + 1 < KT) { stA((kt + 1) & 1); stB((kt + 1) & 1); }
    __syncthreads();
  }

  // transposed fp16 store: g_MT[e][d] = C[d][e]
#pragma unroll
  for (int mi = 0; mi < 2; mi++)
#pragma unroll
    for (int ni = 0; ni < 8; ni++) {
      int r0 = bm * 128 + wm * 32 + mi * 16 + grp;
      int c0 = bn * 128 + wn * 64 + ni * 8 + qd * 2;
      g_MT[(size_t)c0 * N + r0] = __float2half(acc[mi][ni][0] * cscale);
      g_MT[(size_t)(c0 + 1) * N + r0] = __float2half(acc[mi][ni][1] * cscale);
      g_MT[(size_t)c0 * N + r0 + 8] = __float2half(acc[mi][ni][2] * cscale);
      g_MT[(size_t)(c0 + 1) * N + r0 + 8] = __float2half(acc[mi][ni][3] * cscale);
    }
}

// =====================================================================
// copy: grid (8 slices, 256 batches) -> 2048 blocks for full HBM BW.
// Each block gathers+converts 32 compacted ctx rows and 32 cand rows
// (fp32 -> fp16), and computes v' for its cand rows from the raw floats.
// =====================================================================
__global__ void __launch_bounds__(256) copy_kernel(
    const float* __restrict__ ctx, const float* __restrict__ cand,
    const float* __restrict__ WV) {
  __shared__ int lr[32], sr[32];
  const int b = blockIdx.y, slice = blockIdx.x;
  const int t = threadIdx.x, lane = t & 31, w = t >> 5;
  const int cnt = g_cnt[b], cs = g_cnt_s[b], start = g_start[b];
  const int r0 = slice * 32;

  if (t < 32) {
    if (r0 + t < cnt) lr[t] = g_rowmap[start + r0 + t] - b * CL;
    if (r0 + t < cs) sr[t] = g_colmap[b * 256 + r0 + t];
  }
  __syncthreads();

  // ctx rows
  {
    const int nrows = min(32, cnt - r0);
    if (nrows > 0) {
      const float4* src = (const float4*)(ctx + (size_t)b * CL * CD);
      uint2* dst = (uint2*)(g_ctx_c + (size_t)(start + r0) * CD);
      const int tot = nrows * 192;
      for (int idx = t; idx < tot; idx += 256) {
        int r = idx / 192, c = idx - r * 192;
        float4 v = src[lr[r] * 192 + c];
        dst[idx] = make_uint2(pack2h(v.x, v.y), pack2h(v.z, v.w));
      }
    }
  }
  // cand rows + v'
  {
    const int nrows = min(32, cs - r0);
    if (nrows > 0) {
      const float4* src = (const float4*)(cand + (size_t)b * CS * CD);
      uint2* dst = (uint2*)(g_cand_c + ((size_t)b * 256 + r0) * CD);
      const int tot = nrows * 192;
      for (int idx = t; idx < tot; idx += 256) {
        int r = idx / 192, c = idx - r * 192;
        float4 v = src[sr[r] * 192 + c];
        dst[idx] = make_uint2(pack2h(v.x, v.y), pack2h(v.z, v.w));
      }
      const float4* wv4 = (const float4*)WV;
      for (int jj = w; jj < nrows; jj += 8) {
        const float4* row = src + (size_t)sr[jj] * 192;
        float p = 0.f;
#pragma unroll
        for (int k2 = 0; k2 < 6; k2++) {
          float4 x = row[lane + k2 * 32];
          float4 y = wv4[lane + k2 * 32];
          p += x.x * y.x + x.y * y.y + x.z * y.z + x.w * y.w;
        }
#pragma unroll
        for (int o = 16; o > 0; o >>= 1) p += __shfl_xor_sync(~0u, p, o);
        if (lane == 0) g_v[b * 256 + r0 + jj] = p;
      }
    }
  }
}

// =====================================================================
// Unified 128x128xK=768 fp16 mainloop: m16n8k16, ldmatrix b16 fragments,
// 3-stage cp.async (k-chunk 64 halves = 128B/row/stage), 2 CTAs/SM.
// MODE 0 (qgemm):  A = ctx_c rows, B = g_MT,    epilogue: store q'' fp16
// MODE 1 (agemm):  A = q_c rows,   B = cand_c,  epilogue: sigmoid*v -> x
// =====================================================================
template <int MODE>
__global__ void __launch_bounds__(256, 2) mm_main() {
  extern __shared__ char sm[];
  const int tid = threadIdx.x, lane = tid & 31, warp = tid >> 5;
  const int wm = warp >> 1, wn = warp & 1;
  const int grp = lane >> 2, qd = lane & 3;

  const char* Abase;
  const char* Bbase;
  int b = 0, mt = 0, nt = 0, cnt = 0, start = 0;
  if (MODE == 0) {
    int ptot = (g_total + 127) & ~127;
    if ((int)blockIdx.y * 128 >= ptot) return;
    Abase = (const char*)(g_ctx_c + (size_t)blockIdx.y * 128 * CD);
    Bbase = (const char*)(g_MT + (size_t)blockIdx.x * 128 * CD);
  } else {
    b = blockIdx.y; mt = blockIdx.x >> 1; nt = blockIdx.x & 1;
    cnt = g_cnt[b];
    int cs = g_cnt_s[b];
    if (mt * 128 >= cnt || nt * 128 >= cs) return;
    start = g_start[b];
    Abase = (const char*)(g_qc + (size_t)(start + mt * 128) * CD);
    Bbase = (const char*)(g_cand_c + ((size_t)b * 256 + nt * 128) * CD);
  }

  float* v_s = (float*)sm;          // [128]
  float* x_s = (float*)(sm + 512);  // [128]
  char* stg = sm + 1024;
  const uint32_t sb = smem_u32(stg);
  constexpr int RSTR = 144;          // 64 halves (128B) + 16B pad, conflict-free
  constexpr int ASZ = 128 * RSTR;    // 18432
  constexpr int STG = 2 * ASZ;       // 36864
  constexpr int KT = CD / 64;        // 12 k-tiles

  if (MODE == 1 && tid < 128) {
    x_s[tid] = 0.f;
    v_s[tid] = g_v[b * 256 + nt * 128 + tid];
  }

  // ldmatrix per-lane byte offsets (fp16 m16n8k16 canonical x4 pattern)
  const int l7 = lane & 7, lb3 = (lane >> 3) & 1, lb4 = lane >> 4;
  const uint32_t a_base0 = (uint32_t)((wm * 32 + l7 + lb3 * 8) * RSTR + lb4 * 16);
  const uint32_t a_base1 = a_base0 + 16 * RSTR;
  uint32_t b_base[4];
#pragma unroll
  for (int j = 0; j < 4; j++)
    b_base[j] = (uint32_t)((wn * 64 + j * 16 + l7 + lb4 * 8) * RSTR + lb3 * 16);

  float acc[2][8][4];
#pragma unroll
  for (int i = 0; i < 2; i++)
#pragma unroll
    for (int j = 0; j < 8; j++)
#pragma unroll
      for (int t = 0; t < 4; t++) acc[i][j][t] = 0.f;

  auto issue = [&](int kt) {
    if (kt < KT) {
      int s = kt - (kt / 3) * 3;
      uint32_t ab = sb + s * STG, bb = ab + ASZ;
#pragma unroll
      for (int i = 0; i < 4; i++) {
        int f = tid + i * 256, r = f >> 3, c = f & 7;
        cp16(ab + r * RSTR + c * 16, Abase + (size_t)r * 1536 + kt * 128 + c * 16);
        cp16(bb + r * RSTR + c * 16, Bbase + (size_t)r * 1536 + kt * 128 + c * 16);
      }
    }
    CP_COMMIT();
  };

  issue(0);
  issue(1);
  for (int kt = 0; kt < KT; ++kt) {
    CP_WAIT1();
    __syncthreads();
    issue(kt + 2);
    const int s = kt - (kt / 3) * 3;
    const uint32_t abp = sb + s * STG;
    const uint32_t bbp = abp + ASZ;
#pragma unroll
    for (int ks = 0; ks < 4; ks++) {
      const uint32_t ka = ks * 32;  // k16 = 32 bytes
      unsigned a0[4], a1[4];
      LDSM_X4(a0[0], a0[1], a0[2], a0[3], abp + a_base0 + ka);
      LDSM_X4(a1[0], a1[1], a1[2], a1[3], abp + a_base1 + ka);
#pragma unroll
      for (int j = 0; j < 4; j++) {
        unsigned bf0, bf1, bf2, bf3;
        LDSM_X4(bf0, bf1, bf2, bf3, bbp + b_base[j] + ka);
        mma16(acc[0][2 * j], a0, bf0, bf1);
        mma16(acc[1][2 * j], a1, bf0, bf1);
        mma16(acc[0][2 * j + 1], a0, bf2, bf3);
        mma16(acc[1][2 * j + 1], a1, bf2, bf3);
      }
    }
  }

  if (MODE == 0) {
    const int i0 = blockIdx.y * 128, bn = blockIdx.x;
#pragma unroll
    for (int mi = 0; mi < 2; mi++)
#pragma unroll
      for (int ni = 0; ni < 8; ni++) {
        int r = wm * 32 + mi * 16 + grp;
        int c = bn * 128 + wn * 64 + ni * 8 + qd * 2;
        size_t o = (size_t)(i0 + r) * CD + c;
        *(uint32_t*)(g_qc + o) = pack2h(acc[mi][ni][0], acc[mi][ni][1]);
        o += (size_t)8 * CD;
        *(uint32_t*)(g_qc + o) = pack2h(acc[mi][ni][2], acc[mi][ni][3]);
      }
  } else {
    float xp[2][2] = {{0.f, 0.f}, {0.f, 0.f}};
#pragma unroll
    for (int mi = 0; mi < 2; mi++)
#pragma unroll
      for (int ni = 0; ni < 8; ni++) {
        int c0 = wn * 64 + ni * 8 + qd * 2;
        float va = v_s[c0], vb = v_s[c0 + 1];
        xp[mi][0] += va / (1.f + __expf(-acc[mi][ni][0])) + vb / (1.f + __expf(-acc[mi][ni][1]));
        xp[mi][1] += va / (1.f + __expf(-acc[mi][ni][2])) + vb / (1.f + __expf(-acc[mi][ni][3]));
      }
#pragma unroll
    for (int mi = 0; mi < 2; mi++)
#pragma unroll
      for (int rs = 0; rs < 2; rs++) {
        float v = xp[mi][rs];
        v += __shfl_xor_sync(0xffffffffu, v, 1);
        v += __shfl_xor_sync(0xffffffffu, v, 2);
        if (qd == 0) atomicAdd(&x_s[wm * 32 + mi * 16 + rs * 8 + grp], v);
      }
    __syncthreads();
    if (tid < 128 && mt * 128 + tid < cnt)
      atomicAdd(&g_x[g_rowmap[start + mt * 128 + tid]], x_s[tid]);
  }
}

// =====================================================================
// Head: y[b,:] = (x_b @ W1 + b1) @ W2 + b2.
// =====================================================================
__global__ void head_kernel(const float* __restrict__ W1, const float* __restrict__ b1,
                            const float* __restrict__ W2, const float* __restrict__ b2,
                            float* __restrict__ out) {
  __shared__ float xs[CL];
  __shared__ float hs[CH];
  int b = blockIdx.x, tid = threadIdx.x;
  xs[tid] = g_x[b * CL + tid];
  xs[tid + 128] = g_x[b * CL + tid + 128];
  __syncthreads();
  float h = b1[tid];
  for (int l = 0; l < CL; l++) h += xs[l] * W1[l * CH + tid];
  hs[tid] = h;
  __syncthreads();
  if (tid < 5) {
    float y = b2[tid];
    for (int k = 0; k < CH; k++) y += hs[k] * W2[k * 5 + tid];
    out[b * 5 + tid] = y;
  }
}

extern "C" void kernel_launch(void* const* d_in, const int* in_sizes, int n_in,
                              void* d_out, int out_size) {
  const float* ctx = (const float*)d_in[0];
  const float* cand = (const float*)d_in[1];
  const int* ctx_mask = (const int*)d_in[2];
  const int* cand_mask = (const int*)d_in[3];
  const float* WK = (const float*)d_in[4];
  const float* WQ = (const float*)d_in[5];
  const float* WV = (const float*)d_in[6];
  const float* W1 = (const float*)d_in[7];
  const float* b1 = (const float*)d_in[8];
  const float* W2 = (const float*)d_in[9];
  const float* b2 = (const float*)d_in[10];
  float* out = (float*)d_out;
  (void)in_sizes; (void)n_in; (void)out_size;

  constexpr int GEMM_SMEM = (2 * 128 * 36 + 2 * 32 * 132) * 4;  // 70656
  constexpr int MM_SMEM = 1024 + 3 * (2 * 128 * 144);           // 111616

  cudaFuncSetAttribute(fusedA, cudaFuncAttributeMaxDynamicSharedMemorySize, GEMM_SMEM);
  cudaFuncSetAttribute(mm_main<0>, cudaFuncAttributeMaxDynamicSharedMemorySize, MM_SMEM);
  cudaFuncSetAttribute(mm_main<1>, cudaFuncAttributeMaxDynamicSharedMemorySize, MM_SMEM);

  float scale = 1.0f / sqrtf((float)CD);

  // 0: mask counts + prefix
  scan1<<<1, 256>>>(ctx_mask, cand_mask);
  // 1: fused heterogeneous wave: compaction maps (256 blocks) || K0 (36 blocks)
  fusedA<<<292, 256, GEMM_SMEM>>>(WQ, WK, scale, ctx_mask, cand_mask);
  // 2: high-occupancy gather/convert + v'  (2048 blocks)
  copy_kernel<<<dim3(8, CB), 256>>>(ctx, cand, WV);
  // 3 (profiled): q_c = ctx_c @ M  (fp16 mainloop)
  mm_main<0><<<dim3(CD / 128, (CB * CL) / 128), 256, MM_SMEM>>>();
  // 4: fused logits -> sigmoid -> x  (fp16 mainloop)
  mm_main<1><<<dim3(4, CB), 256, MM_SMEM>>>();
  // 5: head MLP -> y
  head_kernel<<<CB, CH>>>(W1, b1, W2, b2, out);
}